// round 1
// baseline (speedup 1.0000x reference)
#include <cuda_runtime.h>

#define NEGV  (-1e20f)
#define Bsz   128
#define TU    256
#define TB    128
#define TP    64
#define HH    512
#define VV    3000
#define VOOVc 3400

// ---------------- scratch (no allocations allowed) ----------------
__device__ float g_q[Bsz*HH];                  // h0 @ W1^T + attn_b
__device__ float g_scores[Bsz*(TU+TB+TP)];     // attention logits (u|b|p)
__device__ float g_x[Bsz*2080];                // [emb | ctx_u | ctx_b | ctx_p | db]
__device__ float g_gi[Bsz*1536];
__device__ float g_gh[Bsz*1536];
__device__ float g_hnew[Bsz*HH];
__device__ float g_gen[Bsz*VV];
__device__ float g_cpraw[Bsz*TB];

// ---------------- generic tiled SGEMM:  C[m,n] = sum_k A[m,k]*B[n,k] ----------------
// EPI==0: C = acc + bias[n]   (store)
// EPI==1: sOut[m] += sum_n dvec[b,n] * tanh(acc + qadd[b,n]),  b = m0/T  (fused score)
#define BMt 64
#define BNt 64
#define BKt 16

template<int EPI>
__global__ __launch_bounds__(256)
void gemm_k(const float* __restrict__ A, int lda,
            const float* __restrict__ Bw, int ldb,
            float* __restrict__ C, int ldc,
            const float* __restrict__ bias,
            int M, int N, int K,
            const float* __restrict__ qadd, int qstride,
            const float* __restrict__ dvec, int dstride,
            float* __restrict__ sOut, int T)
{
    __shared__ float As[BKt][BMt];
    __shared__ float Bs[BKt][BNt];
    const int tid = threadIdx.x;
    const int tx = tid & 15, ty = tid >> 4;
    const int m0 = blockIdx.y * BMt, n0 = blockIdx.x * BNt;
    const int lr = tid >> 2;            // 0..63
    const int lk = (tid & 3) << 2;      // 0,4,8,12

    float acc[4][4];
#pragma unroll
    for (int i = 0; i < 4; i++)
#pragma unroll
        for (int j = 0; j < 4; j++) acc[i][j] = 0.f;

    const bool av_ok = (m0 + lr) < M;
    const bool bv_ok = (n0 + lr) < N;
    const float* Ap = A + (size_t)(m0 + lr) * lda + lk;
    const float* Bp = Bw + (size_t)(n0 + lr) * ldb + lk;

    for (int k0 = 0; k0 < K; k0 += BKt) {
        float4 av = av_ok ? *(const float4*)(Ap + k0) : make_float4(0.f,0.f,0.f,0.f);
        float4 bv = bv_ok ? *(const float4*)(Bp + k0) : make_float4(0.f,0.f,0.f,0.f);
        As[lk+0][lr] = av.x; As[lk+1][lr] = av.y; As[lk+2][lr] = av.z; As[lk+3][lr] = av.w;
        Bs[lk+0][lr] = bv.x; Bs[lk+1][lr] = bv.y; Bs[lk+2][lr] = bv.z; Bs[lk+3][lr] = bv.w;
        __syncthreads();
#pragma unroll
        for (int k = 0; k < BKt; k++) {
            const float4 a4 = *(const float4*)&As[k][ty << 2];
            const float4 b4 = *(const float4*)&Bs[k][tx << 2];
            const float ar[4] = {a4.x, a4.y, a4.z, a4.w};
            const float br[4] = {b4.x, b4.y, b4.z, b4.w};
#pragma unroll
            for (int i = 0; i < 4; i++)
#pragma unroll
                for (int j = 0; j < 4; j++) acc[i][j] += ar[i] * br[j];
        }
        __syncthreads();
    }

    if (EPI == 0) {
#pragma unroll
        for (int i = 0; i < 4; i++) {
            const int m = m0 + (ty << 2) + i;
            if (m >= M) continue;
#pragma unroll
            for (int j = 0; j < 4; j++) {
                const int n = n0 + (tx << 2) + j;
                if (n < N) C[(size_t)m * ldc + n] = acc[i][j] + bias[n];
            }
        }
    } else {
        const int b = m0 / T;   // BM=64 divides every T used -> b constant per tile
        const float* q  = qadd + (size_t)b * qstride;
        const float* dv = dvec + (size_t)b * dstride;
#pragma unroll
        for (int i = 0; i < 4; i++) {
            float s = 0.f;
#pragma unroll
            for (int j = 0; j < 4; j++) {
                const int n = n0 + (tx << 2) + j;
                if (n < N) s += dv[n] * tanhf(acc[i][j] + q[n]);
            }
#pragma unroll
            for (int o = 8; o > 0; o >>= 1) s += __shfl_xor_sync(0xffffffffu, s, o, 16);
            if (tx == 0) {
                const int m = m0 + (ty << 2) + i;
                if (m < M) atomicAdd(&sOut[m], s);
            }
        }
    }
}

// ---------------- small kernels ----------------
__global__ void zero_k()
{
    const int i = blockIdx.x * 256 + threadIdx.x;
    if (i < Bsz * (TU + TB + TP)) g_scores[i] = 0.f;
    if (i < Bsz * TB)             g_cpraw[i]  = 0.f;
}

__global__ void assemble_x(const int* __restrict__ w, const float* __restrict__ emb,
                           const float* __restrict__ db)
{
    const int b = blockIdx.x, tid = threadIdx.x;
    const int wi = w[b];
    g_x[b*2080 + tid]       = emb[(size_t)wi*HH + tid];
    g_x[b*2080 + 256 + tid] = emb[(size_t)wi*HH + 256 + tid];
    if (tid < 32) g_x[b*2080 + 2048 + tid] = db[b*32 + tid];
}

// per-(b, encoder) masked softmax over scores + ctx = a @ enc, written straight into g_x
__global__ __launch_bounds__(256)
void ctx_k(const float* __restrict__ u, const float* __restrict__ bs,
           const float* __restrict__ p, const int* __restrict__ idu,
           const int* __restrict__ idb, const int* __restrict__ idp)
{
    const int b = blockIdx.x, e = blockIdx.y, tid = threadIdx.x;
    const float* enc; const int* ids; int T, soff;
    if (e == 0)      { enc = u;  ids = idu; T = TU; soff = 0; }
    else if (e == 1) { enc = bs; ids = idb; T = TB; soff = Bsz*TU; }
    else             { enc = p;  ids = idp; T = TP; soff = Bsz*(TU+TB); }

    __shared__ float a[TU];
    __shared__ float red[8];

    float s = -3.4e38f;
    if (tid < T) {
        s = g_scores[soff + b*T + tid];
        if (ids[b*T + tid] == 0) s = NEGV;
    }
    float v = s;
#pragma unroll
    for (int o = 16; o; o >>= 1) v = fmaxf(v, __shfl_xor_sync(~0u, v, o));
    if ((tid & 31) == 0) red[tid >> 5] = v;
    __syncthreads();
    float mx = red[0];
#pragma unroll
    for (int i = 1; i < 8; i++) mx = fmaxf(mx, red[i]);
    __syncthreads();

    const float ex = (tid < T) ? expf(s - mx) : 0.f;
    v = ex;
#pragma unroll
    for (int o = 16; o; o >>= 1) v += __shfl_xor_sync(~0u, v, o);
    if ((tid & 31) == 0) red[tid >> 5] = v;
    __syncthreads();
    float sum = 0.f;
#pragma unroll
    for (int i = 0; i < 8; i++) sum += red[i];
    if (tid < T) a[tid] = ex / sum;
    __syncthreads();

    const float* er = enc + (size_t)b * T * HH;
    float a0 = 0.f, a1 = 0.f;
#pragma unroll 4
    for (int t = 0; t < T; t++) {
        const float at = a[t];
        a0 += at * er[t*HH + tid];
        a1 += at * er[t*HH + 256 + tid];
    }
    float* xd = g_x + b*2080 + 512 + e*HH;
    xd[tid] = a0; xd[256 + tid] = a1;
}

__global__ void gate_k(const float* __restrict__ h0)
{
    const int i = blockIdx.x * 256 + threadIdx.x;   // B*H
    const int b = i >> 9, h = i & (HH - 1);
    const float ir  = g_gi[b*1536 + h],       hr = g_gh[b*1536 + h];
    const float iz  = g_gi[b*1536 + 512 + h], hz = g_gh[b*1536 + 512 + h];
    const float in_ = g_gi[b*1536 + 1024 + h],hn = g_gh[b*1536 + 1024 + h];
    const float r = 1.f / (1.f + expf(-(ir + hr)));
    const float z = 1.f / (1.f + expf(-(iz + hz)));
    const float n = tanhf(in_ + r * hn);
    g_hnew[i] = (1.f - z) * n + z * h0[i];
}

// per-b: scatter cps (== onehot matmul), joint log_softmax over [gen|cps] (6128),
// logaddexp for v<V, OOV scatter-add + log for v>=V
__global__ __launch_bounds__(256)
void final_k(const int* __restrict__ idb, const int* __restrict__ nounk,
             float* __restrict__ out)
{
    const int b = blockIdx.x, tid = threadIdx.x;
    __shared__ float cps[VV + TB];          // 3128
    __shared__ float add2[VOOVc - VV];      // 400
    __shared__ float red[8];

    for (int i = tid; i < VV + TB; i += 256) cps[i] = 0.f;
    for (int i = tid; i < VOOVc - VV; i += 256) add2[i] = 0.f;
    __syncthreads();

    if (tid < TB) {
        float cr = g_cpraw[b*TB + tid];
        if (idb[b*TB + tid] == 0) cr = NEGV;
        const int nk = nounk[b*TB + tid];
        const int col = (nk < VV) ? nk : (VV + tid);
        atomicAdd(&cps[col], cr);           // exact one-hot matmul semantics
    }
    __syncthreads();

    const float* gb = g_gen + (size_t)b * VV;
    float mx = -3.4e38f;
    for (int i = tid; i < VV; i += 256)       mx = fmaxf(mx, gb[i]);
    for (int i = tid; i < VV + TB; i += 256)  mx = fmaxf(mx, cps[i]);
    float v = mx;
#pragma unroll
    for (int o = 16; o; o >>= 1) v = fmaxf(v, __shfl_xor_sync(~0u, v, o));
    if ((tid & 31) == 0) red[tid >> 5] = v;
    __syncthreads();
    mx = red[0];
#pragma unroll
    for (int i = 1; i < 8; i++) mx = fmaxf(mx, red[i]);
    __syncthreads();

    float se = 0.f;
    for (int i = tid; i < VV; i += 256)       se += expf(gb[i] - mx);
    for (int i = tid; i < VV + TB; i += 256)  se += expf(cps[i] - mx);
    v = se;
#pragma unroll
    for (int o = 16; o; o >>= 1) v += __shfl_xor_sync(~0u, v, o);
    if ((tid & 31) == 0) red[tid >> 5] = v;
    __syncthreads();
    se = 0.f;
#pragma unroll
    for (int i = 0; i < 8; i++) se += red[i];
    const float lz = mx + logf(se);

    float* ob = out + (size_t)b * VOOVc;
    for (int i = tid; i < VV; i += 256) {
        const float ga = gb[i] - lz, cc = cps[i] - lz;
        const float m2 = fmaxf(ga, cc);
        ob[i] = m2 + log1pf(expf(fminf(ga, cc) - m2));   // logaddexp(gen_s, c2g)
    }
    if (tid < TB) {
        const int nk = nounk[b*TB + tid];
        if (nk >= VV) atomicAdd(&add2[nk - VV], expf(cps[VV + tid] - lz));
    }
    __syncthreads();
    for (int i = tid; i < VOOVc - VV; i += 256) {
        const float a2 = add2[i];
        ob[VV + i] = (a2 > 0.f) ? logf(fmaxf(a2, 1e-38f)) : NEGV;
    }
}

// ---------------- launcher ----------------
extern "C" void kernel_launch(void* const* d_in, const int* in_sizes, int n_in,
                              void* d_out, int out_size)
{
    (void)in_sizes; (void)n_in; (void)out_size;
    const int*   w     = (const int*)  d_in[0];
    const float* h0    = (const float*)d_in[1];   // (1,B,H) == (B,H)
    const float* usdx  = (const float*)d_in[2];
    const float* bspn  = (const float*)d_in[3];
    const float* pv    = (const float*)d_in[4];
    const float* db    = (const float*)d_in[5];
    const int*   idu   = (const int*)  d_in[6];
    const int*   idb   = (const int*)  d_in[7];
    const int*   idp   = (const int*)  d_in[8];
    const int*   nounk = (const int*)  d_in[9];
    // d_in[10] = bspn_onehot: deliberately unused (replaced by exact scatter on nounk)
    const float* emb   = (const float*)d_in[11];
    const float* attnW = (const float*)d_in[12];  // (H, 2H): W1 = [:, :H], W2 = [:, H:]
    const float* attnb = (const float*)d_in[13];
    const float* vw    = (const float*)d_in[14];
    const float* Wc    = (const float*)d_in[15];
    const float* Wcb   = (const float*)d_in[16];
    const float* Wg    = (const float*)d_in[17];
    const float* Wgb   = (const float*)d_in[18];
    const float* Wih   = (const float*)d_in[19];
    const float* Whh   = (const float*)d_in[20];
    const float* bih   = (const float*)d_in[21];
    const float* bhh   = (const float*)d_in[22];
    float* out = (float*)d_out;

    float *q, *sc, *x, *gi, *gh, *hn, *gen, *cpr;
    cudaGetSymbolAddress((void**)&q,   g_q);
    cudaGetSymbolAddress((void**)&sc,  g_scores);
    cudaGetSymbolAddress((void**)&x,   g_x);
    cudaGetSymbolAddress((void**)&gi,  g_gi);
    cudaGetSymbolAddress((void**)&gh,  g_gh);
    cudaGetSymbolAddress((void**)&hn,  g_hnew);
    cudaGetSymbolAddress((void**)&gen, g_gen);
    cudaGetSymbolAddress((void**)&cpr, g_cpraw);

    zero_k<<<(Bsz*(TU+TB+TP) + 255) / 256, 256>>>();

    // q[b,h] = h0 @ W1^T + attn_b
    gemm_k<0><<<dim3(8, 2), 256>>>(h0, HH, attnW, 2*HH, q, HH, attnb,
                                   Bsz, HH, HH, nullptr, 0, nullptr, 0, nullptr, 1);
    assemble_x<<<Bsz, 256>>>(w, emb, db);

    // fused attention logits: score[b,t] = sum_h v[h]*tanh(q[b,h] + enc@W2^T)
    gemm_k<1><<<dim3(8, Bsz*TU/64), 256>>>(usdx, HH, attnW + HH, 2*HH, nullptr, 0, nullptr,
                                           Bsz*TU, HH, HH, q, HH, vw, 0, sc, TU);
    gemm_k<1><<<dim3(8, Bsz*TB/64), 256>>>(bspn, HH, attnW + HH, 2*HH, nullptr, 0, nullptr,
                                           Bsz*TB, HH, HH, q, HH, vw, 0, sc + Bsz*TU, TB);
    gemm_k<1><<<dim3(8, Bsz*TP/64), 256>>>(pv, HH, attnW + HH, 2*HH, nullptr, 0, nullptr,
                                           Bsz*TP, HH, HH, q, HH, vw, 0, sc + Bsz*(TU+TB), TP);

    ctx_k<<<dim3(Bsz, 3), 256>>>(usdx, bspn, pv, idu, idb, idp);

    // GRU
    gemm_k<0><<<dim3(24, 2), 256>>>(x, 2080, Wih, 2080, gi, 1536, bih,
                                    Bsz, 1536, 2080, nullptr, 0, nullptr, 0, nullptr, 1);
    gemm_k<0><<<dim3(24, 2), 256>>>(h0, HH, Whh, HH, gh, 1536, bhh,
                                    Bsz, 1536, HH, nullptr, 0, nullptr, 0, nullptr, 1);
    gate_k<<<Bsz*HH/256, 256>>>(h0);

    // gen = hnew @ Wgen^T + b
    gemm_k<0><<<dim3((VV + 63) / 64, 2), 256>>>(hn, HH, Wg, HH, gen, VV, Wgb,
                                                Bsz, VV, HH, nullptr, 0, nullptr, 0, nullptr, 1);
    // cp_raw[b,t] = sum_h hnew[b,h]*tanh(bspn@Wcopy^T + cb)
    gemm_k<1><<<dim3(8, Bsz*TB/64), 256>>>(bspn, HH, Wc, HH, nullptr, 0, nullptr,
                                           Bsz*TB, HH, HH, Wcb, 0, hn, HH, cpr, TB);

    final_k<<<Bsz, 256>>>(idb, nounk, out);
}

// round 2
// speedup vs baseline: 1.3404x; 1.3404x over previous
#include <cuda_runtime.h>

#define NEGV  (-1e20f)
#define Bsz   128
#define TU    256
#define TB    128
#define TP    64
#define HH    512
#define VV    3000
#define VOOVc 3400

// ---------------- scratch (no allocations allowed) ----------------
__device__ float g_q[Bsz*HH];                  // h0 @ W1^T + attn_b
__device__ float g_scores[Bsz*(TU+TB+TP)];     // attention logits (u|b|p)
__device__ float g_x[Bsz*2080];                // [emb | ctx_u | ctx_b | ctx_p | db]
__device__ float g_gi[Bsz*1536];
__device__ float g_gh[Bsz*1536];
__device__ float g_hnew[Bsz*HH];
__device__ float g_gen[Bsz*VV];
__device__ float g_cpraw[Bsz*TB];

// =====================================================================
// BIG fused-score GEMM: 128x128x16 tiles, 8x8 microtile (2x2 blocks of 4).
// Requirements: M%128==0, N%128==0, K%16==0 (all score GEMMs satisfy).
// Computes: sOut[m] += sum_n dvec[b(m),n] * tanh( (A@B^T)[m,n] + qadd[b(m),n] )
//   with b(m) = m / T.
// =====================================================================
#define BMb 128
#define BNb 128
#define BKb 16

__global__ __launch_bounds__(256, 2)
void score_gemm(const float* __restrict__ A, int lda,
                const float* __restrict__ Bw, int ldb,
                int K,
                const float* __restrict__ qadd, int qstride,
                const float* __restrict__ dvec, int dstride,
                float* __restrict__ sOut, int T)
{
    __shared__ float As[BKb][BMb];
    __shared__ float Bs[BKb][BNb];

    const int tid = threadIdx.x;
    const int tx = tid & 15, ty = tid >> 4;
    const int m0 = blockIdx.y * BMb, n0 = blockIdx.x * BNb;

    const int r0 = tid >> 2;             // 0..63
    const int kq = (tid & 3) << 2;       // 0,4,8,12

    const float* Ap = A  + (size_t)(m0 + r0) * lda + kq;
    const float* Bp = Bw + (size_t)(n0 + r0) * ldb + kq;
    const size_t a64 = (size_t)64 * lda;
    const size_t b64 = (size_t)64 * ldb;

    float acc[8][8];
#pragma unroll
    for (int i = 0; i < 8; i++)
#pragma unroll
        for (int j = 0; j < 8; j++) acc[i][j] = 0.f;

    // prefetch first k-block
    float4 pa0 = *(const float4*)(Ap);
    float4 pa1 = *(const float4*)(Ap + a64);
    float4 pb0 = *(const float4*)(Bp);
    float4 pb1 = *(const float4*)(Bp + b64);

    for (int k0 = 0; k0 < K; k0 += BKb) {
        // store prefetched block to shared
        As[kq+0][r0] = pa0.x; As[kq+1][r0] = pa0.y; As[kq+2][r0] = pa0.z; As[kq+3][r0] = pa0.w;
        As[kq+0][r0+64] = pa1.x; As[kq+1][r0+64] = pa1.y; As[kq+2][r0+64] = pa1.z; As[kq+3][r0+64] = pa1.w;
        Bs[kq+0][r0] = pb0.x; Bs[kq+1][r0] = pb0.y; Bs[kq+2][r0] = pb0.z; Bs[kq+3][r0] = pb0.w;
        Bs[kq+0][r0+64] = pb1.x; Bs[kq+1][r0+64] = pb1.y; Bs[kq+2][r0+64] = pb1.z; Bs[kq+3][r0+64] = pb1.w;
        __syncthreads();

        if (k0 + BKb < K) {
            const int kn = k0 + BKb;
            pa0 = *(const float4*)(Ap + kn);
            pa1 = *(const float4*)(Ap + a64 + kn);
            pb0 = *(const float4*)(Bp + kn);
            pb1 = *(const float4*)(Bp + b64 + kn);
        }

#pragma unroll
        for (int k = 0; k < BKb; k++) {
            const float4 a0 = *(const float4*)&As[k][ty << 2];
            const float4 a1 = *(const float4*)&As[k][64 + (ty << 2)];
            const float4 b0 = *(const float4*)&Bs[k][tx << 2];
            const float4 b1 = *(const float4*)&Bs[k][64 + (tx << 2)];
            const float ar[8] = {a0.x,a0.y,a0.z,a0.w,a1.x,a1.y,a1.z,a1.w};
            const float br[8] = {b0.x,b0.y,b0.z,b0.w,b1.x,b1.y,b1.z,b1.w};
#pragma unroll
            for (int i = 0; i < 8; i++)
#pragma unroll
                for (int j = 0; j < 8; j++) acc[i][j] += ar[i] * br[j];
        }
        __syncthreads();
    }

    // epilogue: s[m] += sum_n dv[n]*tanh(acc + q[n]); rows i<4 -> m0+ty*4+i, i>=4 -> +64
#pragma unroll
    for (int rg = 0; rg < 2; rg++) {
        const int mbase = m0 + rg * 64 + (ty << 2);
        const int b = mbase / T;                    // constant over the 4 rows (64 | T grouping)
        const float* q  = qadd + (size_t)b * qstride;
        const float* dv = dvec + (size_t)b * dstride;
        const float4 q0 = *(const float4*)(q + n0 + (tx << 2));
        const float4 q1 = *(const float4*)(q + n0 + 64 + (tx << 2));
        const float4 d0 = *(const float4*)(dv + n0 + (tx << 2));
        const float4 d1 = *(const float4*)(dv + n0 + 64 + (tx << 2));
        const float qr[8] = {q0.x,q0.y,q0.z,q0.w,q1.x,q1.y,q1.z,q1.w};
        const float dr[8] = {d0.x,d0.y,d0.z,d0.w,d1.x,d1.y,d1.z,d1.w};
#pragma unroll
        for (int i = 0; i < 4; i++) {
            float s = 0.f;
#pragma unroll
            for (int j = 0; j < 8; j++)
                s += dr[j] * tanhf(acc[rg*4 + i][j] + qr[j]);
#pragma unroll
            for (int o = 8; o > 0; o >>= 1) s += __shfl_xor_sync(0xffffffffu, s, o, 16);
            if (tx == 0) atomicAdd(&sOut[mbase + i], s);
        }
    }
}

// ---------------- generic tiled SGEMM (small-M cases): C = A@B^T + bias ----------------
#define BMt 64
#define BNt 64
#define BKt 16

__global__ __launch_bounds__(256)
void gemm_k(const float* __restrict__ A, int lda,
            const float* __restrict__ Bw, int ldb,
            float* __restrict__ C, int ldc,
            const float* __restrict__ bias,
            int M, int N, int K)
{
    __shared__ float As[BKt][BMt];
    __shared__ float Bs[BKt][BNt];
    const int tid = threadIdx.x;
    const int tx = tid & 15, ty = tid >> 4;
    const int m0 = blockIdx.y * BMt, n0 = blockIdx.x * BNt;
    const int lr = tid >> 2;
    const int lk = (tid & 3) << 2;

    float acc[4][4];
#pragma unroll
    for (int i = 0; i < 4; i++)
#pragma unroll
        for (int j = 0; j < 4; j++) acc[i][j] = 0.f;

    const bool av_ok = (m0 + lr) < M;
    const bool bv_ok = (n0 + lr) < N;
    const float* Ap = A + (size_t)(m0 + lr) * lda + lk;
    const float* Bp = Bw + (size_t)(n0 + lr) * ldb + lk;

    for (int k0 = 0; k0 < K; k0 += BKt) {
        float4 av = av_ok ? *(const float4*)(Ap + k0) : make_float4(0.f,0.f,0.f,0.f);
        float4 bv = bv_ok ? *(const float4*)(Bp + k0) : make_float4(0.f,0.f,0.f,0.f);
        As[lk+0][lr] = av.x; As[lk+1][lr] = av.y; As[lk+2][lr] = av.z; As[lk+3][lr] = av.w;
        Bs[lk+0][lr] = bv.x; Bs[lk+1][lr] = bv.y; Bs[lk+2][lr] = bv.z; Bs[lk+3][lr] = bv.w;
        __syncthreads();
#pragma unroll
        for (int k = 0; k < BKt; k++) {
            const float4 a4 = *(const float4*)&As[k][ty << 2];
            const float4 b4 = *(const float4*)&Bs[k][tx << 2];
            const float ar[4] = {a4.x, a4.y, a4.z, a4.w};
            const float br[4] = {b4.x, b4.y, b4.z, b4.w};
#pragma unroll
            for (int i = 0; i < 4; i++)
#pragma unroll
                for (int j = 0; j < 4; j++) acc[i][j] += ar[i] * br[j];
        }
        __syncthreads();
    }

#pragma unroll
    for (int i = 0; i < 4; i++) {
        const int m = m0 + (ty << 2) + i;
        if (m >= M) continue;
#pragma unroll
        for (int j = 0; j < 4; j++) {
            const int n = n0 + (tx << 2) + j;
            if (n < N) C[(size_t)m * ldc + n] = acc[i][j] + bias[n];
        }
    }
}

// ---------------- small kernels ----------------
__global__ void zero_k()
{
    const int i = blockIdx.x * 256 + threadIdx.x;
    if (i < Bsz * (TU + TB + TP)) g_scores[i] = 0.f;
    if (i < Bsz * TB)             g_cpraw[i]  = 0.f;
}

__global__ void assemble_x(const int* __restrict__ w, const float* __restrict__ emb,
                           const float* __restrict__ db)
{
    const int b = blockIdx.x, tid = threadIdx.x;
    const int wi = w[b];
    g_x[b*2080 + tid]       = emb[(size_t)wi*HH + tid];
    g_x[b*2080 + 256 + tid] = emb[(size_t)wi*HH + 256 + tid];
    if (tid < 32) g_x[b*2080 + 2048 + tid] = db[b*32 + tid];
}

// per-(b, encoder) masked softmax over scores + ctx = a @ enc, written straight into g_x
__global__ __launch_bounds__(256)
void ctx_k(const float* __restrict__ u, const float* __restrict__ bs,
           const float* __restrict__ p, const int* __restrict__ idu,
           const int* __restrict__ idb, const int* __restrict__ idp)
{
    const int b = blockIdx.x, e = blockIdx.y, tid = threadIdx.x;
    const float* enc; const int* ids; int T, soff;
    if (e == 0)      { enc = u;  ids = idu; T = TU; soff = 0; }
    else if (e == 1) { enc = bs; ids = idb; T = TB; soff = Bsz*TU; }
    else             { enc = p;  ids = idp; T = TP; soff = Bsz*(TU+TB); }

    __shared__ float a[TU];
    __shared__ float red[8];

    float s = -3.4e38f;
    if (tid < T) {
        s = g_scores[soff + b*T + tid];
        if (ids[b*T + tid] == 0) s = NEGV;
    }
    float v = s;
#pragma unroll
    for (int o = 16; o; o >>= 1) v = fmaxf(v, __shfl_xor_sync(~0u, v, o));
    if ((tid & 31) == 0) red[tid >> 5] = v;
    __syncthreads();
    float mx = red[0];
#pragma unroll
    for (int i = 1; i < 8; i++) mx = fmaxf(mx, red[i]);
    __syncthreads();

    const float ex = (tid < T) ? expf(s - mx) : 0.f;
    v = ex;
#pragma unroll
    for (int o = 16; o; o >>= 1) v += __shfl_xor_sync(~0u, v, o);
    if ((tid & 31) == 0) red[tid >> 5] = v;
    __syncthreads();
    float sum = 0.f;
#pragma unroll
    for (int i = 0; i < 8; i++) sum += red[i];
    if (tid < T) a[tid] = ex / sum;
    __syncthreads();

    const float* er = enc + (size_t)b * T * HH;
    float a0 = 0.f, a1 = 0.f;
#pragma unroll 4
    for (int t = 0; t < T; t++) {
        const float at = a[t];
        a0 += at * er[t*HH + tid];
        a1 += at * er[t*HH + 256 + tid];
    }
    float* xd = g_x + b*2080 + 512 + e*HH;
    xd[tid] = a0; xd[256 + tid] = a1;
}

__global__ void gate_k(const float* __restrict__ h0)
{
    const int i = blockIdx.x * 256 + threadIdx.x;   // B*H
    const int b = i >> 9, h = i & (HH - 1);
    const float ir  = g_gi[b*1536 + h],       hr = g_gh[b*1536 + h];
    const float iz  = g_gi[b*1536 + 512 + h], hz = g_gh[b*1536 + 512 + h];
    const float in_ = g_gi[b*1536 + 1024 + h],hn = g_gh[b*1536 + 1024 + h];
    const float r = 1.f / (1.f + expf(-(ir + hr)));
    const float z = 1.f / (1.f + expf(-(iz + hz)));
    const float n = tanhf(in_ + r * hn);
    g_hnew[i] = (1.f - z) * n + z * h0[i];
}

// per-b: scatter cps (== onehot matmul), joint log_softmax over [gen|cps],
// logaddexp for v<V, OOV scatter-add + log for v>=V
__global__ __launch_bounds__(256)
void final_k(const int* __restrict__ idb, const int* __restrict__ nounk,
             float* __restrict__ out)
{
    const int b = blockIdx.x, tid = threadIdx.x;
    __shared__ float cps[VV + TB];
    __shared__ float add2[VOOVc - VV];
    __shared__ float red[8];

    for (int i = tid; i < VV + TB; i += 256) cps[i] = 0.f;
    for (int i = tid; i < VOOVc - VV; i += 256) add2[i] = 0.f;
    __syncthreads();

    if (tid < TB) {
        float cr = g_cpraw[b*TB + tid];
        if (idb[b*TB + tid] == 0) cr = NEGV;
        const int nk = nounk[b*TB + tid];
        const int col = (nk < VV) ? nk : (VV + tid);
        atomicAdd(&cps[col], cr);
    }
    __syncthreads();

    const float* gb = g_gen + (size_t)b * VV;
    float mx = -3.4e38f;
    for (int i = tid; i < VV; i += 256)       mx = fmaxf(mx, gb[i]);
    for (int i = tid; i < VV + TB; i += 256)  mx = fmaxf(mx, cps[i]);
    float v = mx;
#pragma unroll
    for (int o = 16; o; o >>= 1) v = fmaxf(v, __shfl_xor_sync(~0u, v, o));
    if ((tid & 31) == 0) red[tid >> 5] = v;
    __syncthreads();
    mx = red[0];
#pragma unroll
    for (int i = 1; i < 8; i++) mx = fmaxf(mx, red[i]);
    __syncthreads();

    float se = 0.f;
    for (int i = tid; i < VV; i += 256)       se += expf(gb[i] - mx);
    for (int i = tid; i < VV + TB; i += 256)  se += expf(cps[i] - mx);
    v = se;
#pragma unroll
    for (int o = 16; o; o >>= 1) v += __shfl_xor_sync(~0u, v, o);
    if ((tid & 31) == 0) red[tid >> 5] = v;
    __syncthreads();
    se = 0.f;
#pragma unroll
    for (int i = 0; i < 8; i++) se += red[i];
    const float lz = mx + logf(se);

    float* ob = out + (size_t)b * VOOVc;
    for (int i = tid; i < VV; i += 256) {
        const float ga = gb[i] - lz, cc = cps[i] - lz;
        const float m2 = fmaxf(ga, cc);
        ob[i] = m2 + log1pf(expf(fminf(ga, cc) - m2));
    }
    if (tid < TB) {
        const int nk = nounk[b*TB + tid];
        if (nk >= VV) atomicAdd(&add2[nk - VV], expf(cps[VV + tid] - lz));
    }
    __syncthreads();
    for (int i = tid; i < VOOVc - VV; i += 256) {
        const float a2 = add2[i];
        ob[VV + i] = (a2 > 0.f) ? logf(fmaxf(a2, 1e-38f)) : NEGV;
    }
}

// ---------------- launcher ----------------
extern "C" void kernel_launch(void* const* d_in, const int* in_sizes, int n_in,
                              void* d_out, int out_size)
{
    (void)in_sizes; (void)n_in; (void)out_size;
    const int*   w     = (const int*)  d_in[0];
    const float* h0    = (const float*)d_in[1];
    const float* usdx  = (const float*)d_in[2];
    const float* bspn  = (const float*)d_in[3];
    const float* pv    = (const float*)d_in[4];
    const float* db    = (const float*)d_in[5];
    const int*   idu   = (const int*)  d_in[6];
    const int*   idb   = (const int*)  d_in[7];
    const int*   idp   = (const int*)  d_in[8];
    const int*   nounk = (const int*)  d_in[9];
    const float* emb   = (const float*)d_in[11];
    const float* attnW = (const float*)d_in[12];
    const float* attnb = (const float*)d_in[13];
    const float* vw    = (const float*)d_in[14];
    const float* Wc    = (const float*)d_in[15];
    const float* Wcb   = (const float*)d_in[16];
    const float* Wg    = (const float*)d_in[17];
    const float* Wgb   = (const float*)d_in[18];
    const float* Wih   = (const float*)d_in[19];
    const float* Whh   = (const float*)d_in[20];
    const float* bih   = (const float*)d_in[21];
    const float* bhh   = (const float*)d_in[22];
    float* out = (float*)d_out;

    float *q, *sc, *x, *gi, *gh, *hn, *gen, *cpr;
    cudaGetSymbolAddress((void**)&q,   g_q);
    cudaGetSymbolAddress((void**)&sc,  g_scores);
    cudaGetSymbolAddress((void**)&x,   g_x);
    cudaGetSymbolAddress((void**)&gi,  g_gi);
    cudaGetSymbolAddress((void**)&gh,  g_gh);
    cudaGetSymbolAddress((void**)&hn,  g_hnew);
    cudaGetSymbolAddress((void**)&gen, g_gen);
    cudaGetSymbolAddress((void**)&cpr, g_cpraw);

    zero_k<<<(Bsz*(TU+TB+TP) + 255) / 256, 256>>>();

    // q[b,h] = h0 @ W1^T + attn_b
    gemm_k<<<dim3(8, 2), 256>>>(h0, HH, attnW, 2*HH, q, HH, attnb, Bsz, HH, HH);
    assemble_x<<<Bsz, 256>>>(w, emb, db);

    // fused attention logits: score[b,t] = sum_h v[h]*tanh(q[b,h] + enc@W2^T)
    score_gemm<<<dim3(4, Bsz*TU/128), 256>>>(usdx, HH, attnW + HH, 2*HH, HH,
                                             q, HH, vw, 0, sc, TU);
    score_gemm<<<dim3(4, Bsz*TB/128), 256>>>(bspn, HH, attnW + HH, 2*HH, HH,
                                             q, HH, vw, 0, sc + Bsz*TU, TB);
    score_gemm<<<dim3(4, Bsz*TP/128), 256>>>(pv, HH, attnW + HH, 2*HH, HH,
                                             q, HH, vw, 0, sc + Bsz*(TU+TB), TP);

    ctx_k<<<dim3(Bsz, 3), 256>>>(usdx, bspn, pv, idu, idb, idp);

    // GRU
    gemm_k<<<dim3(24, 2), 256>>>(x, 2080, Wih, 2080, gi, 1536, bih, Bsz, 1536, 2080);
    gemm_k<<<dim3(24, 2), 256>>>(h0, HH, Whh, HH, gh, 1536, bhh, Bsz, 1536, HH);
    gate_k<<<Bsz*HH/256, 256>>>(h0);

    // gen = hnew @ Wgen^T + b
    gemm_k<<<dim3((VV + 63) / 64, 2), 256>>>(hn, HH, Wg, HH, gen, VV, Wgb, Bsz, VV, HH);
    // cp_raw[b,t] = sum_h hnew[b,h]*tanh(bspn@Wcopy^T + cb)
    score_gemm<<<dim3(4, Bsz*TB/128), 256>>>(bspn, HH, Wc, HH, HH,
                                             Wcb, 0, hn, HH, cpr, TB);

    final_k<<<Bsz, 256>>>(idb, nounk, out);
}

// round 4
// speedup vs baseline: 2.5308x; 1.8881x over previous
#include <cuda_runtime.h>
#include <cuda_bf16.h>

#define NEGV  (-1e20f)
#define Bsz   128
#define TU    256
#define TB    128
#define TP    64
#define HH    512
#define VV    3000
#define VOOVc 3400

// ---------------- scratch (no allocations allowed) ----------------
__device__ float g_q[Bsz*HH];
__device__ float g_scores[Bsz*(TU+TB+TP)];
__device__ float g_x[Bsz*2080];
__device__ float g_gi[Bsz*1536];
__device__ float g_gh[Bsz*1536];
__device__ float g_hnew[Bsz*HH];
__device__ float g_gen[Bsz*VV];
__device__ float g_cpraw[Bsz*TB];

// =====================================================================
// bf16 HMMA GEMM: C = A @ B^T, 128x128x32 tiles, mma.sync.m16n8k16.
// A: [M,K] fp32 row-major (M%128==0), B: [N,K] fp32 row-major (rows
// zero-filled past N), K%32==0.
// EPI==0: C[m,n] = acc + bias[n]                      (n<N guarded)
// EPI==1: sOut[m] += sum_n dvec[b,n]*tanh(acc + qadd[b,n]),  b=m/T
// =====================================================================
#define PADK 40   // bf16 elems per smem row (32 data + 8 pad)

__device__ __forceinline__ unsigned pk(float a, float b) {
    __nv_bfloat162 t = __floats2bfloat162_rn(a, b);
    return *(unsigned*)&t;
}

template<int EPI>
__global__ __launch_bounds__(256)
void mma_gemm(const float* __restrict__ A, int lda,
              const float* __restrict__ Bw, int ldb,
              float* __restrict__ C, int ldc,
              const float* __restrict__ bias,
              int M, int N, int K,
              const float* __restrict__ qadd, int qstride,
              const float* __restrict__ dvec, int dstride,
              float* __restrict__ sOut, int T)
{
    __shared__ __nv_bfloat16 As[128 * PADK];
    __shared__ __nv_bfloat16 Bs[128 * PADK];

    const int tid = threadIdx.x;
    const int wid = tid >> 5, lane = tid & 31;
    const int wm = wid >> 2, wn = wid & 3;        // 2 x 4 warp grid
    const int g = lane >> 2, tig = lane & 3;
    const int m0 = blockIdx.y * 128, n0 = blockIdx.x * 128;

    // tile-load mapping: thread t loads 16 floats of row (t>>1), kseg=(t&1)*16
    const int lrow = tid >> 1;
    const int kseg = (tid & 1) << 4;
    const float* Ap = A + (size_t)(m0 + lrow) * lda + kseg;
    const bool bok = (n0 + lrow) < N;
    const float* Bp = Bw + (size_t)(n0 + lrow) * ldb + kseg;
    uint4* aDst = (uint4*)&As[lrow * PADK + kseg];
    uint4* bDst = (uint4*)&Bs[lrow * PADK + kseg];

    float acc[4][4][4];
#pragma unroll
    for (int i = 0; i < 4; i++)
#pragma unroll
        for (int j = 0; j < 4; j++)
#pragma unroll
            for (int c = 0; c < 4; c++) acc[i][j][c] = 0.f;

    const unsigned* A32 = (const unsigned*)As;
    const unsigned* B32 = (const unsigned*)Bs;

    for (int k0 = 0; k0 < K; k0 += 32) {
        // load + convert A tile
        {
            float4 v0 = *(const float4*)(Ap + k0);
            float4 v1 = *(const float4*)(Ap + k0 + 4);
            float4 v2 = *(const float4*)(Ap + k0 + 8);
            float4 v3 = *(const float4*)(Ap + k0 + 12);
            aDst[0] = make_uint4(pk(v0.x,v0.y), pk(v0.z,v0.w), pk(v1.x,v1.y), pk(v1.z,v1.w));
            aDst[1] = make_uint4(pk(v2.x,v2.y), pk(v2.z,v2.w), pk(v3.x,v3.y), pk(v3.z,v3.w));
            float4 w0, w1, w2, w3;
            if (bok) {
                w0 = *(const float4*)(Bp + k0);
                w1 = *(const float4*)(Bp + k0 + 4);
                w2 = *(const float4*)(Bp + k0 + 8);
                w3 = *(const float4*)(Bp + k0 + 12);
            } else {
                w0 = w1 = w2 = w3 = make_float4(0.f,0.f,0.f,0.f);
            }
            bDst[0] = make_uint4(pk(w0.x,w0.y), pk(w0.z,w0.w), pk(w1.x,w1.y), pk(w1.z,w1.w));
            bDst[1] = make_uint4(pk(w2.x,w2.y), pk(w2.z,w2.w), pk(w3.x,w3.y), pk(w3.z,w3.w));
        }
        __syncthreads();

#pragma unroll
        for (int ks = 0; ks < 2; ks++) {
            unsigned afr[4][4], bfr[4][2];
#pragma unroll
            for (int mf = 0; mf < 4; mf++) {
                const int base = (wm*64 + mf*16 + g) * (PADK/2) + ks*8 + tig;
                afr[mf][0] = A32[base];
                afr[mf][1] = A32[base + 8*(PADK/2)];
                afr[mf][2] = A32[base + 4];
                afr[mf][3] = A32[base + 8*(PADK/2) + 4];
            }
#pragma unroll
            for (int nf = 0; nf < 4; nf++) {
                const int base = (wn*32 + nf*8 + g) * (PADK/2) + ks*8 + tig;
                bfr[nf][0] = B32[base];
                bfr[nf][1] = B32[base + 4];
            }
#pragma unroll
            for (int mf = 0; mf < 4; mf++)
#pragma unroll
                for (int nf = 0; nf < 4; nf++) {
                    asm volatile(
                        "mma.sync.aligned.m16n8k16.row.col.f32.bf16.bf16.f32 "
                        "{%0,%1,%2,%3},{%4,%5,%6,%7},{%8,%9},{%0,%1,%2,%3};"
                        : "+f"(acc[mf][nf][0]), "+f"(acc[mf][nf][1]),
                          "+f"(acc[mf][nf][2]), "+f"(acc[mf][nf][3])
                        : "r"(afr[mf][0]), "r"(afr[mf][1]), "r"(afr[mf][2]), "r"(afr[mf][3]),
                          "r"(bfr[nf][0]), "r"(bfr[nf][1]));
                }
        }
        __syncthreads();
    }

    if (EPI == 0) {
#pragma unroll
        for (int mf = 0; mf < 4; mf++)
#pragma unroll
            for (int rr = 0; rr < 2; rr++) {
                const int m = m0 + wm*64 + mf*16 + g + rr*8;
                if (m >= M) continue;
#pragma unroll
                for (int nf = 0; nf < 4; nf++) {
                    const int n = n0 + wn*32 + nf*8 + 2*tig;
                    if (n < N)     C[(size_t)m*ldc + n]     = acc[mf][nf][rr*2]   + bias[n];
                    if (n + 1 < N) C[(size_t)m*ldc + n + 1] = acc[mf][nf][rr*2+1] + bias[n+1];
                }
            }
    } else {
#pragma unroll
        for (int mf = 0; mf < 4; mf++)
#pragma unroll
            for (int rr = 0; rr < 2; rr++) {
                const int m = m0 + wm*64 + mf*16 + g + rr*8;
                const int b = m / T;
                const float* q  = qadd + (size_t)b * qstride;
                const float* dv = dvec + (size_t)b * dstride;
                float s = 0.f;
#pragma unroll
                for (int nf = 0; nf < 4; nf++) {
                    const int n = n0 + wn*32 + nf*8 + 2*tig;
                    s += dv[n]   * tanhf(acc[mf][nf][rr*2]   + q[n]);
                    s += dv[n+1] * tanhf(acc[mf][nf][rr*2+1] + q[n+1]);
                }
                s += __shfl_xor_sync(0xffffffffu, s, 1);
                s += __shfl_xor_sync(0xffffffffu, s, 2);
                if (tig == 0) atomicAdd(&sOut[m], s);
            }
    }
}

// ---------------- small kernels ----------------
__global__ void zero_k()
{
    const int i = blockIdx.x * 256 + threadIdx.x;
    if (i < Bsz * (TU + TB + TP)) g_scores[i] = 0.f;
    if (i < Bsz * TB)             g_cpraw[i]  = 0.f;
}

__global__ void assemble_x(const int* __restrict__ w, const float* __restrict__ emb,
                           const float* __restrict__ db)
{
    const int b = blockIdx.x, tid = threadIdx.x;
    const int wi = w[b];
    g_x[b*2080 + tid]       = emb[(size_t)wi*HH + tid];
    g_x[b*2080 + 256 + tid] = emb[(size_t)wi*HH + 256 + tid];
    if (tid < 32) g_x[b*2080 + 2048 + tid] = db[b*32 + tid];
}

__global__ __launch_bounds__(256)
void ctx_k(const float* __restrict__ u, const float* __restrict__ bs,
           const float* __restrict__ p, const int* __restrict__ idu,
           const int* __restrict__ idb, const int* __restrict__ idp)
{
    const int b = blockIdx.x, e = blockIdx.y, tid = threadIdx.x;
    const float* enc; const int* ids; int T, soff;
    if (e == 0)      { enc = u;  ids = idu; T = TU; soff = 0; }
    else if (e == 1) { enc = bs; ids = idb; T = TB; soff = Bsz*TU; }
    else             { enc = p;  ids = idp; T = TP; soff = Bsz*(TU+TB); }

    __shared__ float a[TU];
    __shared__ float red[8];

    float s = -3.4e38f;
    if (tid < T) {
        s = g_scores[soff + b*T + tid];
        if (ids[b*T + tid] == 0) s = NEGV;
    }
    float v = s;
#pragma unroll
    for (int o = 16; o; o >>= 1) v = fmaxf(v, __shfl_xor_sync(~0u, v, o));
    if ((tid & 31) == 0) red[tid >> 5] = v;
    __syncthreads();
    float mx = red[0];
#pragma unroll
    for (int i = 1; i < 8; i++) mx = fmaxf(mx, red[i]);
    __syncthreads();

    const float ex = (tid < T) ? expf(s - mx) : 0.f;
    v = ex;
#pragma unroll
    for (int o = 16; o; o >>= 1) v += __shfl_xor_sync(~0u, v, o);
    if ((tid & 31) == 0) red[tid >> 5] = v;
    __syncthreads();
    float sum = 0.f;
#pragma unroll
    for (int i = 0; i < 8; i++) sum += red[i];
    if (tid < T) a[tid] = ex / sum;
    __syncthreads();

    const float* er = enc + (size_t)b * T * HH;
    float a0 = 0.f, a1 = 0.f;
#pragma unroll 4
    for (int t = 0; t < T; t++) {
        const float at = a[t];
        a0 += at * er[t*HH + tid];
        a1 += at * er[t*HH + 256 + tid];
    }
    float* xd = g_x + b*2080 + 512 + e*HH;
    xd[tid] = a0; xd[256 + tid] = a1;
}

__global__ void gate_k(const float* __restrict__ h0)
{
    const int i = blockIdx.x * 256 + threadIdx.x;
    const int b = i >> 9, h = i & (HH - 1);
    const float ir  = g_gi[b*1536 + h],       hr = g_gh[b*1536 + h];
    const float iz  = g_gi[b*1536 + 512 + h], hz = g_gh[b*1536 + 512 + h];
    const float in_ = g_gi[b*1536 + 1024 + h],hn = g_gh[b*1536 + 1024 + h];
    const float r = 1.f / (1.f + expf(-(ir + hr)));
    const float z = 1.f / (1.f + expf(-(iz + hz)));
    const float n = tanhf(in_ + r * hn);
    g_hnew[i] = (1.f - z) * n + z * h0[i];
}

__global__ __launch_bounds__(256)
void final_k(const int* __restrict__ idb, const int* __restrict__ nounk,
             float* __restrict__ out)
{
    const int b = blockIdx.x, tid = threadIdx.x;
    __shared__ float cps[VV + TB];
    __shared__ float add2[VOOVc - VV];
    __shared__ float red[8];

    for (int i = tid; i < VV + TB; i += 256) cps[i] = 0.f;
    for (int i = tid; i < VOOVc - VV; i += 256) add2[i] = 0.f;
    __syncthreads();

    if (tid < TB) {
        float cr = g_cpraw[b*TB + tid];
        if (idb[b*TB + tid] == 0) cr = NEGV;
        const int nk = nounk[b*TB + tid];
        const int col = (nk < VV) ? nk : (VV + tid);
        atomicAdd(&cps[col], cr);
    }
    __syncthreads();

    const float* gb = g_gen + (size_t)b * VV;
    float mx = -3.4e38f;
    for (int i = tid; i < VV; i += 256)       mx = fmaxf(mx, gb[i]);
    for (int i = tid; i < VV + TB; i += 256)  mx = fmaxf(mx, cps[i]);
    float v = mx;
#pragma unroll
    for (int o = 16; o; o >>= 1) v = fmaxf(v, __shfl_xor_sync(~0u, v, o));
    if ((tid & 31) == 0) red[tid >> 5] = v;
    __syncthreads();
    mx = red[0];
#pragma unroll
    for (int i = 1; i < 8; i++) mx = fmaxf(mx, red[i]);
    __syncthreads();

    float se = 0.f;
    for (int i = tid; i < VV; i += 256)       se += expf(gb[i] - mx);
    for (int i = tid; i < VV + TB; i += 256)  se += expf(cps[i] - mx);
    v = se;
#pragma unroll
    for (int o = 16; o; o >>= 1) v += __shfl_xor_sync(~0u, v, o);
    if ((tid & 31) == 0) red[tid >> 5] = v;
    __syncthreads();
    se = 0.f;
#pragma unroll
    for (int i = 0; i < 8; i++) se += red[i];
    const float lz = mx + logf(se);

    float* ob = out + (size_t)b * VOOVc;
    for (int i = tid; i < VV; i += 256) {
        const float ga = gb[i] - lz, cc = cps[i] - lz;
        const float m2 = fmaxf(ga, cc);
        ob[i] = m2 + log1pf(expf(fminf(ga, cc) - m2));
    }
    if (tid < TB) {
        const int nk = nounk[b*TB + tid];
        if (nk >= VV) atomicAdd(&add2[nk - VV], expf(cps[VV + tid] - lz));
    }
    __syncthreads();
    for (int i = tid; i < VOOVc - VV; i += 256) {
        const float a2 = add2[i];
        ob[VV + i] = (a2 > 0.f) ? logf(fmaxf(a2, 1e-38f)) : NEGV;
    }
}

// ---------------- launcher ----------------
extern "C" void kernel_launch(void* const* d_in, const int* in_sizes, int n_in,
                              void* d_out, int out_size)
{
    (void)in_sizes; (void)n_in; (void)out_size;
    const int*   w     = (const int*)  d_in[0];
    const float* h0    = (const float*)d_in[1];
    const float* usdx  = (const float*)d_in[2];
    const float* bspn  = (const float*)d_in[3];
    const float* pv    = (const float*)d_in[4];
    const float* db    = (const float*)d_in[5];
    const int*   idu   = (const int*)  d_in[6];
    const int*   idb   = (const int*)  d_in[7];
    const int*   idp   = (const int*)  d_in[8];
    const int*   nounk = (const int*)  d_in[9];
    const float* emb   = (const float*)d_in[11];
    const float* attnW = (const float*)d_in[12];
    const float* attnb = (const float*)d_in[13];
    const float* vw    = (const float*)d_in[14];
    const float* Wc    = (const float*)d_in[15];
    const float* Wcb   = (const float*)d_in[16];
    const float* Wg    = (const float*)d_in[17];
    const float* Wgb   = (const float*)d_in[18];
    const float* Wih   = (const float*)d_in[19];
    const float* Whh   = (const float*)d_in[20];
    const float* bih   = (const float*)d_in[21];
    const float* bhh   = (const float*)d_in[22];
    float* out = (float*)d_out;

    float *q, *sc, *x, *gi, *gh, *hn, *gen, *cpr;
    cudaGetSymbolAddress((void**)&q,   g_q);
    cudaGetSymbolAddress((void**)&sc,  g_scores);
    cudaGetSymbolAddress((void**)&x,   g_x);
    cudaGetSymbolAddress((void**)&gi,  g_gi);
    cudaGetSymbolAddress((void**)&gh,  g_gh);
    cudaGetSymbolAddress((void**)&hn,  g_hnew);
    cudaGetSymbolAddress((void**)&gen, g_gen);
    cudaGetSymbolAddress((void**)&cpr, g_cpraw);

    zero_k<<<(Bsz*(TU+TB+TP) + 255) / 256, 256>>>();

    // q[b,h] = h0 @ W1^T + attn_b
    mma_gemm<0><<<dim3(4, 1), 256>>>(h0, HH, attnW, 2*HH, q, HH, attnb,
                                     Bsz, HH, HH, nullptr, 0, nullptr, 0, nullptr, 1);
    assemble_x<<<Bsz, 256>>>(w, emb, db);

    // fused attention logits: score[b,t] = sum_h v[h]*tanh(q[b,h] + enc@W2^T)
    mma_gemm<1><<<dim3(4, Bsz*TU/128), 256>>>(usdx, HH, attnW + HH, 2*HH, nullptr, 0, nullptr,
                                              Bsz*TU, HH, HH, q, HH, vw, 0, sc, TU);
    mma_gemm<1><<<dim3(4, Bsz*TB/128), 256>>>(bspn, HH, attnW + HH, 2*HH, nullptr, 0, nullptr,
                                              Bsz*TB, HH, HH, q, HH, vw, 0, sc + Bsz*TU, TB);
    mma_gemm<1><<<dim3(4, Bsz*TP/128), 256>>>(pv, HH, attnW + HH, 2*HH, nullptr, 0, nullptr,
                                              Bsz*TP, HH, HH, q, HH, vw, 0, sc + Bsz*(TU+TB), TP);

    ctx_k<<<dim3(Bsz, 3), 256>>>(usdx, bspn, pv, idu, idb, idp);

    // GRU
    mma_gemm<0><<<dim3(12, 1), 256>>>(x, 2080, Wih, 2080, gi, 1536, bih,
                                      Bsz, 1536, 2080, nullptr, 0, nullptr, 0, nullptr, 1);
    mma_gemm<0><<<dim3(12, 1), 256>>>(h0, HH, Whh, HH, gh, 1536, bhh,
                                      Bsz, 1536, HH, nullptr, 0, nullptr, 0, nullptr, 1);
    gate_k<<<Bsz*HH/256, 256>>>(h0);

    // gen = hnew @ Wgen^T + b
    mma_gemm<0><<<dim3(24, 1), 256>>>(hn, HH, Wg, HH, gen, VV, Wgb,
                                      Bsz, VV, HH, nullptr, 0, nullptr, 0, nullptr, 1);
    // cp_raw[b,t] = sum_h hnew[b,h]*tanh(bspn@Wcopy^T + cb)
    mma_gemm<1><<<dim3(4, Bsz*TB/128), 256>>>(bspn, HH, Wc, HH, nullptr, 0, nullptr,
                                              Bsz*TB, HH, HH, Wcb, 0, hn, HH, cpr, TB);

    final_k<<<Bsz, 256>>>(idb, nounk, out);
}

// round 5
// speedup vs baseline: 4.1431x; 1.6371x over previous
#include <cuda_runtime.h>
#include <cuda_bf16.h>

#define NEGV  (-1e20f)
#define Bsz   128
#define TU    256
#define TB    128
#define TP    64
#define HH    512
#define VV    3000
#define VOOVc 3400

typedef __nv_bfloat16 bf16;

// ---------------- fp32 scratch ----------------
__device__ float g_q[Bsz*HH];
__device__ float g_scores[Bsz*(TU+TB+TP)];
__device__ float g_gi[Bsz*1536];
__device__ float g_gh[Bsz*1536];
__device__ float g_hnew[Bsz*HH];
__device__ float g_gen[Bsz*VV];
__device__ float g_cpraw[Bsz*TB];

// ---------------- bf16 scratch (pre-converted operands) ----------------
__device__ bf16 gb_usdx[Bsz*TU*HH];
__device__ bf16 gb_bspn[Bsz*TB*HH];
__device__ bf16 gb_pv  [Bsz*TP*HH];
__device__ bf16 gb_attnW[HH*2*HH];
__device__ bf16 gb_Wc  [HH*HH];
__device__ bf16 gb_Wg  [3072*HH];        // padded 3000 -> 3072 rows
__device__ bf16 gb_Wih [1536*2080];
__device__ bf16 gb_Whh [1536*HH];
__device__ bf16 gb_h0  [Bsz*HH];
__device__ bf16 gb_x   [Bsz*2080];
__device__ bf16 gb_hnew[Bsz*HH];

// ---------------- fp32 -> bf16 convert (with zero-pad to ntot) ----------------
__global__ void cvt_k(const float* __restrict__ s, bf16* __restrict__ d, int n, int ntot)
{
    const int i = (blockIdx.x * 256 + threadIdx.x) * 4;
    if (i < n) {
        const float4 v = *(const float4*)(s + i);
        __nv_bfloat162 lo = __floats2bfloat162_rn(v.x, v.y);
        __nv_bfloat162 hi = __floats2bfloat162_rn(v.z, v.w);
        *(uint2*)(d + i) = make_uint2(*(unsigned*)&lo, *(unsigned*)&hi);
    } else if (i < ntot) {
        *(uint2*)(d + i) = make_uint2(0u, 0u);
    }
}

// =====================================================================
// bf16 HMMA GEMM, cp.async double-buffered, ldmatrix fragments.
// C = A @ B^T.  A:[M,K] bf16 (M = 128*gridDim.y exactly), B:[>=128*gridDim.x, K]
// bf16 (padded valid rows), K%32==0.
// EPI==0: C[m,n] = acc + bias[n]  (n<N guarded on store)
// EPI==1: sOut[m] += sum_n dvec[b,n]*tanh(acc + qadd[b,n]), b=m/T
// =====================================================================
#define PADK 40
#define STGB (128*PADK*2)      // bytes per stage per matrix (10240)

__device__ __forceinline__ void cpa16(unsigned d, const void* s) {
    asm volatile("cp.async.cg.shared.global [%0], [%1], 16;" :: "r"(d), "l"(s));
}
__device__ __forceinline__ void ldsm4(unsigned* r, unsigned a) {
    asm volatile("ldmatrix.sync.aligned.m8n8.x4.shared.b16 {%0,%1,%2,%3}, [%4];"
                 : "=r"(r[0]), "=r"(r[1]), "=r"(r[2]), "=r"(r[3]) : "r"(a));
}

template<int EPI>
__global__ __launch_bounds__(256, 2)
void mma_gemm(const bf16* __restrict__ A, int lda,
              const bf16* __restrict__ Bw, int ldb,
              float* __restrict__ C, int ldc,
              const float* __restrict__ bias,
              int N, int K,
              const float* __restrict__ qadd, int qstride,
              const float* __restrict__ dvec, int dstride,
              float* __restrict__ sOut, int T)
{
    __shared__ bf16 smem[4*128*PADK];   // [A st0 | A st1 | B st0 | B st1]

    const int tid = threadIdx.x, lane = tid & 31, wid = tid >> 5;
    const int wm = wid >> 2, wn = wid & 3;
    const int g = lane >> 2, tig = lane & 3;
    const int m0 = blockIdx.y * 128, n0 = blockIdx.x * 128;
    const unsigned sbase = (unsigned)__cvta_generic_to_shared(smem);

    // cp.async mapping: 512 16B-chunks per matrix; thread handles rows tid>>2 and +64
    const int crow = tid >> 2, ci = tid & 3;
    const bf16* aS0 = A  + (size_t)(m0 + crow)      * lda + ci*8;
    const bf16* aS1 = A  + (size_t)(m0 + crow + 64) * lda + ci*8;
    const bf16* bS0 = Bw + (size_t)(n0 + crow)      * ldb + ci*8;
    const bf16* bS1 = Bw + (size_t)(n0 + crow + 64) * ldb + ci*8;
    const unsigned o0 = (crow * PADK + ci*8) * 2;
    const unsigned o1 = ((crow + 64) * PADK + ci*8) * 2;

    // fragment base addresses (bytes), per thread
    const unsigned aF = sbase +
        ((wm*64 + (lane & 15)) * PADK + ((lane >> 4) * 8)) * 2;
    const unsigned bF = sbase + 2*STGB +
        ((wn*32 + ((lane >> 4) * 8) + (lane & 7)) * PADK + (((lane >> 3) & 1) * 8)) * 2;

    float acc[4][4][4];
#pragma unroll
    for (int i = 0; i < 4; i++)
#pragma unroll
        for (int j = 0; j < 4; j++)
#pragma unroll
            for (int c = 0; c < 4; c++) acc[i][j][c] = 0.f;

    const int KT = K >> 5;

    // prologue: load stage 0
    {
        const unsigned as = sbase, bs = sbase + 2*STGB;
        cpa16(as + o0, aS0); cpa16(as + o1, aS1);
        cpa16(bs + o0, bS0); cpa16(bs + o1, bS1);
        asm volatile("cp.async.commit_group;");
    }

    for (int kt = 0; kt < KT; kt++) {
        const int st = kt & 1;
        if (kt + 1 < KT) {
            const int k1 = (kt + 1) << 5;
            const unsigned as = sbase + (st ^ 1) * STGB;
            const unsigned bs = sbase + 2*STGB + (st ^ 1) * STGB;
            cpa16(as + o0, aS0 + k1); cpa16(as + o1, aS1 + k1);
            cpa16(bs + o0, bS0 + k1); cpa16(bs + o1, bS1 + k1);
            asm volatile("cp.async.commit_group;");
            asm volatile("cp.async.wait_group 1;");
        } else {
            asm volatile("cp.async.wait_group 0;");
        }
        __syncthreads();

        const unsigned aB = aF + st * STGB;
        const unsigned bB = bF + st * STGB;
#pragma unroll
        for (int ks = 0; ks < 2; ks++) {
            unsigned afr[4][4], bfr[4][2];
#pragma unroll
            for (int mf = 0; mf < 4; mf++)
                ldsm4(afr[mf], aB + mf * (16*PADK*2) + ks * 32);
#pragma unroll
            for (int p = 0; p < 2; p++) {
                unsigned r[4];
                ldsm4(r, bB + p * (16*PADK*2) + ks * 32);
                bfr[2*p][0] = r[0]; bfr[2*p][1] = r[1];
                bfr[2*p+1][0] = r[2]; bfr[2*p+1][1] = r[3];
            }
#pragma unroll
            for (int mf = 0; mf < 4; mf++)
#pragma unroll
                for (int nf = 0; nf < 4; nf++) {
                    asm volatile(
                        "mma.sync.aligned.m16n8k16.row.col.f32.bf16.bf16.f32 "
                        "{%0,%1,%2,%3},{%4,%5,%6,%7},{%8,%9},{%0,%1,%2,%3};"
                        : "+f"(acc[mf][nf][0]), "+f"(acc[mf][nf][1]),
                          "+f"(acc[mf][nf][2]), "+f"(acc[mf][nf][3])
                        : "r"(afr[mf][0]), "r"(afr[mf][1]), "r"(afr[mf][2]), "r"(afr[mf][3]),
                          "r"(bfr[nf][0]), "r"(bfr[nf][1]));
                }
        }
        __syncthreads();
    }

    if (EPI == 0) {
#pragma unroll
        for (int mf = 0; mf < 4; mf++)
#pragma unroll
            for (int rr = 0; rr < 2; rr++) {
                const int m = m0 + wm*64 + mf*16 + g + rr*8;
#pragma unroll
                for (int nf = 0; nf < 4; nf++) {
                    const int n = n0 + wn*32 + nf*8 + 2*tig;
                    if (n < N)     C[(size_t)m*ldc + n]     = acc[mf][nf][rr*2]   + bias[n];
                    if (n + 1 < N) C[(size_t)m*ldc + n + 1] = acc[mf][nf][rr*2+1] + bias[n+1];
                }
            }
    } else {
#pragma unroll
        for (int mf = 0; mf < 4; mf++)
#pragma unroll
            for (int rr = 0; rr < 2; rr++) {
                const int m = m0 + wm*64 + mf*16 + g + rr*8;
                const int b = m / T;
                const float* q  = qadd + (size_t)b * qstride;
                const float* dv = dvec + (size_t)b * dstride;
                float s = 0.f;
#pragma unroll
                for (int nf = 0; nf < 4; nf++) {
                    const int n = n0 + wn*32 + nf*8 + 2*tig;
                    s += dv[n]   * tanhf(acc[mf][nf][rr*2]   + q[n]);
                    s += dv[n+1] * tanhf(acc[mf][nf][rr*2+1] + q[n+1]);
                }
                s += __shfl_xor_sync(0xffffffffu, s, 1);
                s += __shfl_xor_sync(0xffffffffu, s, 2);
                if (tig == 0) atomicAdd(&sOut[m], s);
            }
    }
}

// ---------------- small kernels ----------------
__global__ void zero_k()
{
    const int i = blockIdx.x * 256 + threadIdx.x;
    if (i < Bsz * (TU + TB + TP)) g_scores[i] = 0.f;
    if (i < Bsz * TB)             g_cpraw[i]  = 0.f;
}

__global__ void assemble_x(const int* __restrict__ w, const float* __restrict__ emb,
                           const float* __restrict__ db)
{
    const int b = blockIdx.x, tid = threadIdx.x;
    const int wi = w[b];
    gb_x[b*2080 + tid]       = __float2bfloat16(emb[(size_t)wi*HH + tid]);
    gb_x[b*2080 + 256 + tid] = __float2bfloat16(emb[(size_t)wi*HH + 256 + tid]);
    if (tid < 32) gb_x[b*2080 + 2048 + tid] = __float2bfloat16(db[b*32 + tid]);
}

// masked softmax over scores + ctx = a @ enc (bf16 enc), written into gb_x
__global__ __launch_bounds__(256)
void ctx_k(const int* __restrict__ idu, const int* __restrict__ idb,
           const int* __restrict__ idp)
{
    const int b = blockIdx.x, e = blockIdx.y, tid = threadIdx.x;
    const bf16* enc; const int* ids; int T, soff;
    if (e == 0)      { enc = gb_usdx; ids = idu; T = TU; soff = 0; }
    else if (e == 1) { enc = gb_bspn; ids = idb; T = TB; soff = Bsz*TU; }
    else             { enc = gb_pv;   ids = idp; T = TP; soff = Bsz*(TU+TB); }

    __shared__ float a[TU];
    __shared__ float red[8];

    float s = -3.4e38f;
    if (tid < T) {
        s = g_scores[soff + b*T + tid];
        if (ids[b*T + tid] == 0) s = NEGV;
    }
    float v = s;
#pragma unroll
    for (int o = 16; o; o >>= 1) v = fmaxf(v, __shfl_xor_sync(~0u, v, o));
    if ((tid & 31) == 0) red[tid >> 5] = v;
    __syncthreads();
    float mx = red[0];
#pragma unroll
    for (int i = 1; i < 8; i++) mx = fmaxf(mx, red[i]);
    __syncthreads();

    const float ex = (tid < T) ? expf(s - mx) : 0.f;
    v = ex;
#pragma unroll
    for (int o = 16; o; o >>= 1) v += __shfl_xor_sync(~0u, v, o);
    if ((tid & 31) == 0) red[tid >> 5] = v;
    __syncthreads();
    float sum = 0.f;
#pragma unroll
    for (int i = 0; i < 8; i++) sum += red[i];
    if (tid < T) a[tid] = ex / sum;
    __syncthreads();

    const bf16* er = enc + (size_t)b * T * HH;
    float a0 = 0.f, a1 = 0.f;
#pragma unroll 4
    for (int t = 0; t < T; t++) {
        const float at = a[t];
        a0 += at * __bfloat162float(er[t*HH + tid]);
        a1 += at * __bfloat162float(er[t*HH + 256 + tid]);
    }
    bf16* xd = gb_x + b*2080 + 512 + e*HH;
    xd[tid] = __float2bfloat16(a0);
    xd[256 + tid] = __float2bfloat16(a1);
}

__global__ void gate_k(const float* __restrict__ h0)
{
    const int i = blockIdx.x * 256 + threadIdx.x;
    const int b = i >> 9, h = i & (HH - 1);
    const float ir  = g_gi[b*1536 + h],       hr = g_gh[b*1536 + h];
    const float iz  = g_gi[b*1536 + 512 + h], hz = g_gh[b*1536 + 512 + h];
    const float in_ = g_gi[b*1536 + 1024 + h],hn = g_gh[b*1536 + 1024 + h];
    const float r = 1.f / (1.f + expf(-(ir + hr)));
    const float z = 1.f / (1.f + expf(-(iz + hz)));
    const float n = tanhf(in_ + r * hn);
    const float hv = (1.f - z) * n + z * h0[i];
    g_hnew[i] = hv;
    gb_hnew[i] = __float2bfloat16(hv);
}

__global__ __launch_bounds__(256)
void final_k(const int* __restrict__ idb, const int* __restrict__ nounk,
             float* __restrict__ out)
{
    const int b = blockIdx.x, tid = threadIdx.x;
    __shared__ float cps[VV + TB];
    __shared__ float add2[VOOVc - VV];
    __shared__ float red[8];

    for (int i = tid; i < VV + TB; i += 256) cps[i] = 0.f;
    for (int i = tid; i < VOOVc - VV; i += 256) add2[i] = 0.f;
    __syncthreads();

    if (tid < TB) {
        float cr = g_cpraw[b*TB + tid];
        if (idb[b*TB + tid] == 0) cr = NEGV;
        const int nk = nounk[b*TB + tid];
        const int col = (nk < VV) ? nk : (VV + tid);
        atomicAdd(&cps[col], cr);
    }
    __syncthreads();

    const float* gb = g_gen + (size_t)b * VV;
    float mx = -3.4e38f;
    for (int i = tid; i < VV; i += 256)       mx = fmaxf(mx, gb[i]);
    for (int i = tid; i < VV + TB; i += 256)  mx = fmaxf(mx, cps[i]);
    float v = mx;
#pragma unroll
    for (int o = 16; o; o >>= 1) v = fmaxf(v, __shfl_xor_sync(~0u, v, o));
    if ((tid & 31) == 0) red[tid >> 5] = v;
    __syncthreads();
    mx = red[0];
#pragma unroll
    for (int i = 1; i < 8; i++) mx = fmaxf(mx, red[i]);
    __syncthreads();

    float se = 0.f;
    for (int i = tid; i < VV; i += 256)       se += expf(gb[i] - mx);
    for (int i = tid; i < VV + TB; i += 256)  se += expf(cps[i] - mx);
    v = se;
#pragma unroll
    for (int o = 16; o; o >>= 1) v += __shfl_xor_sync(~0u, v, o);
    if ((tid & 31) == 0) red[tid >> 5] = v;
    __syncthreads();
    se = 0.f;
#pragma unroll
    for (int i = 0; i < 8; i++) se += red[i];
    const float lz = mx + logf(se);

    float* ob = out + (size_t)b * VOOVc;
    for (int i = tid; i < VV; i += 256) {
        const float ga = gb[i] - lz, cc = cps[i] - lz;
        const float m2 = fmaxf(ga, cc);
        ob[i] = m2 + log1pf(expf(fminf(ga, cc) - m2));
    }
    if (tid < TB) {
        const int nk = nounk[b*TB + tid];
        if (nk >= VV) atomicAdd(&add2[nk - VV], expf(cps[VV + tid] - lz));
    }
    __syncthreads();
    for (int i = tid; i < VOOVc - VV; i += 256) {
        const float a2 = add2[i];
        ob[VV + i] = (a2 > 0.f) ? logf(fmaxf(a2, 1e-38f)) : NEGV;
    }
}

// ---------------- launcher ----------------
static inline int cgrid(int ntot) { return (ntot / 4 + 255) / 256; }

extern "C" void kernel_launch(void* const* d_in, const int* in_sizes, int n_in,
                              void* d_out, int out_size)
{
    (void)in_sizes; (void)n_in; (void)out_size;
    const int*   w     = (const int*)  d_in[0];
    const float* h0    = (const float*)d_in[1];
    const float* usdx  = (const float*)d_in[2];
    const float* bspn  = (const float*)d_in[3];
    const float* pv    = (const float*)d_in[4];
    const float* db    = (const float*)d_in[5];
    const int*   idu   = (const int*)  d_in[6];
    const int*   idb   = (const int*)  d_in[7];
    const int*   idp   = (const int*)  d_in[8];
    const int*   nounk = (const int*)  d_in[9];
    const float* emb   = (const float*)d_in[11];
    const float* attnW = (const float*)d_in[12];
    const float* attnb = (const float*)d_in[13];
    const float* vw    = (const float*)d_in[14];
    const float* Wc    = (const float*)d_in[15];
    const float* Wcb   = (const float*)d_in[16];
    const float* Wg    = (const float*)d_in[17];
    const float* Wgb   = (const float*)d_in[18];
    const float* Wih   = (const float*)d_in[19];
    const float* Whh   = (const float*)d_in[20];
    const float* bih   = (const float*)d_in[21];
    const float* bhh   = (const float*)d_in[22];
    float* out = (float*)d_out;

    float *q, *sc, *gi, *gh, *hn, *gen, *cpr;
    bf16 *bU, *bB, *bP, *bAW, *bWc, *bWg, *bWih, *bWhh, *bH0, *bX, *bHn;
    cudaGetSymbolAddress((void**)&q,   g_q);
    cudaGetSymbolAddress((void**)&sc,  g_scores);
    cudaGetSymbolAddress((void**)&gi,  g_gi);
    cudaGetSymbolAddress((void**)&gh,  g_gh);
    cudaGetSymbolAddress((void**)&hn,  g_hnew);
    cudaGetSymbolAddress((void**)&gen, g_gen);
    cudaGetSymbolAddress((void**)&cpr, g_cpraw);
    cudaGetSymbolAddress((void**)&bU,  gb_usdx);
    cudaGetSymbolAddress((void**)&bB,  gb_bspn);
    cudaGetSymbolAddress((void**)&bP,  gb_pv);
    cudaGetSymbolAddress((void**)&bAW, gb_attnW);
    cudaGetSymbolAddress((void**)&bWc, gb_Wc);
    cudaGetSymbolAddress((void**)&bWg, gb_Wg);
    cudaGetSymbolAddress((void**)&bWih,gb_Wih);
    cudaGetSymbolAddress((void**)&bWhh,gb_Whh);
    cudaGetSymbolAddress((void**)&bH0, gb_h0);
    cudaGetSymbolAddress((void**)&bX,  gb_x);
    cudaGetSymbolAddress((void**)&bHn, gb_hnew);

    zero_k<<<(Bsz*(TU+TB+TP) + 255) / 256, 256>>>();

    // conversions
    cvt_k<<<cgrid(Bsz*TU*HH), 256>>>(usdx, bU, Bsz*TU*HH, Bsz*TU*HH);
    cvt_k<<<cgrid(Bsz*TB*HH), 256>>>(bspn, bB, Bsz*TB*HH, Bsz*TB*HH);
    cvt_k<<<cgrid(Bsz*TP*HH), 256>>>(pv,   bP, Bsz*TP*HH, Bsz*TP*HH);
    cvt_k<<<cgrid(HH*2*HH),   256>>>(attnW,bAW,HH*2*HH,   HH*2*HH);
    cvt_k<<<cgrid(HH*HH),     256>>>(Wc,   bWc,HH*HH,     HH*HH);
    cvt_k<<<cgrid(3072*HH),   256>>>(Wg,   bWg,VV*HH,     3072*HH);
    cvt_k<<<cgrid(1536*2080), 256>>>(Wih,  bWih,1536*2080,1536*2080);
    cvt_k<<<cgrid(1536*HH),   256>>>(Whh,  bWhh,1536*HH,  1536*HH);
    cvt_k<<<cgrid(Bsz*HH),    256>>>(h0,   bH0, Bsz*HH,   Bsz*HH);

    // q = h0 @ W1^T + attn_b
    mma_gemm<0><<<dim3(4, 1), 256>>>(bH0, HH, bAW, 2*HH, q, HH, attnb,
                                     HH, HH, nullptr, 0, nullptr, 0, nullptr, 1);
    assemble_x<<<Bsz, 256>>>(w, emb, db);

    // fused attention logits
    mma_gemm<1><<<dim3(4, Bsz*TU/128), 256>>>(bU, HH, bAW + HH, 2*HH, nullptr, 0, nullptr,
                                              HH, HH, q, HH, vw, 0, sc, TU);
    mma_gemm<1><<<dim3(4, Bsz*TB/128), 256>>>(bB, HH, bAW + HH, 2*HH, nullptr, 0, nullptr,
                                              HH, HH, q, HH, vw, 0, sc + Bsz*TU, TB);
    mma_gemm<1><<<dim3(4, Bsz*TP/128), 256>>>(bP, HH, bAW + HH, 2*HH, nullptr, 0, nullptr,
                                              HH, HH, q, HH, vw, 0, sc + Bsz*(TU+TB), TP);

    ctx_k<<<dim3(Bsz, 3), 256>>>(idu, idb, idp);

    // GRU
    mma_gemm<0><<<dim3(12, 1), 256>>>(bX, 2080, bWih, 2080, gi, 1536, bih,
                                      1536, 2080, nullptr, 0, nullptr, 0, nullptr, 1);
    mma_gemm<0><<<dim3(12, 1), 256>>>(bH0, HH, bWhh, HH, gh, 1536, bhh,
                                      1536, HH, nullptr, 0, nullptr, 0, nullptr, 1);
    gate_k<<<Bsz*HH/256, 256>>>(h0);

    // gen = hnew @ Wgen^T + b
    mma_gemm<0><<<dim3(24, 1), 256>>>(bHn, HH, bWg, HH, gen, VV, Wgb,
                                      VV, HH, nullptr, 0, nullptr, 0, nullptr, 1);
    // cp_raw
    mma_gemm<1><<<dim3(4, Bsz*TB/128), 256>>>(bB, HH, bWc, HH, nullptr, 0, nullptr,
                                              HH, HH, Wcb, 0, hn, HH, cpr, TB);

    final_k<<<Bsz, 256>>>(idb, nounk, out);
}

// round 7
// speedup vs baseline: 5.3477x; 1.2907x over previous
#include <cuda_runtime.h>
#include <cuda_bf16.h>

#define NEGV  (-1e20f)
#define Bsz   128
#define TU    256
#define TB    128
#define TP    64
#define HH    512
#define VV    3000
#define VOOVc 3400

typedef __nv_bfloat16 bf16;

// ---------------- fp32 scratch ----------------
__device__ float g_q[Bsz*HH];                // pre-init = attn_b, then += h0@W1^T
__device__ float g_scores[Bsz*(TU+TB+TP)];
__device__ float g_gi[Bsz*1536];             // pre-zero, += x@Wih^T
__device__ float g_gh[Bsz*1536];             // pre-zero, += h0@Whh^T
__device__ float g_hnew[Bsz*HH];
__device__ float g_gen[Bsz*VV];              // pre-init = Wgen_b, then += hnew@Wg^T
__device__ float g_cpraw[Bsz*TB];

// ---------------- bf16 scratch ----------------
__device__ bf16 gb_usdx[Bsz*TU*HH];
__device__ bf16 gb_bspn[Bsz*TB*HH];
__device__ bf16 gb_pv  [Bsz*TP*HH];
__device__ bf16 gb_attnW[HH*2*HH];
__device__ bf16 gb_Wc  [HH*HH];
__device__ bf16 gb_Wg  [3072*HH];            // padded 3000 -> 3072 rows
__device__ bf16 gb_Wih [1536*2080];
__device__ bf16 gb_Whh [1536*HH];
__device__ bf16 gb_h0  [Bsz*HH];
__device__ bf16 gb_x   [Bsz*2080];
__device__ bf16 gb_hnew[Bsz*HH];

// =====================================================================
// megacvt: ALL fp32->bf16 conversions + scratch inits in ONE kernel.
// Unit = 4 elements. Cumulative ranges (compile-time).
// =====================================================================
#define C_USDX  (Bsz*TU*HH/4)
#define C_BSPN  (C_USDX + Bsz*TB*HH/4)
#define C_PV    (C_BSPN + Bsz*TP*HH/4)
#define C_AW    (C_PV   + HH*2*HH/4)
#define C_WC    (C_AW   + HH*HH/4)
#define C_WG    (C_WC   + 3072*HH/4)
#define C_WIH   (C_WG   + 1536*2080/4)
#define C_WHH   (C_WIH  + 1536*HH/4)
#define C_H0    (C_WHH  + Bsz*HH/4)
#define C_Q     (C_H0   + Bsz*HH/4)
#define C_GEN   (C_Q    + Bsz*VV/4)
#define C_ZS    (C_GEN  + Bsz*(TU+TB+TP)/4)
#define C_ZC    (C_ZS   + Bsz*TB/4)
#define C_ZGI   (C_ZC   + Bsz*1536/4)
#define C_ZGH   (C_ZGI  + Bsz*1536/4)

__device__ __forceinline__ void cv4(const float* __restrict__ s, bf16* __restrict__ d, int i)
{
    const float4 v = *(const float4*)(s + 4*(size_t)i);
    __nv_bfloat162 lo = __floats2bfloat162_rn(v.x, v.y);
    __nv_bfloat162 hi = __floats2bfloat162_rn(v.z, v.w);
    *(uint2*)(d + 4*(size_t)i) = make_uint2(*(unsigned*)&lo, *(unsigned*)&hi);
}

__global__ __launch_bounds__(256)
void megacvt(const float* __restrict__ usdx, const float* __restrict__ bspn,
             const float* __restrict__ pv,   const float* __restrict__ aw,
             const float* __restrict__ wc,   const float* __restrict__ wg,
             const float* __restrict__ wih,  const float* __restrict__ whh,
             const float* __restrict__ h0,   const float* __restrict__ attnb,
             const float* __restrict__ wgb)
{
    const int stride = gridDim.x * blockDim.x;
    for (int i = blockIdx.x * blockDim.x + threadIdx.x; i < C_ZGH; i += stride) {
        if (i < C_USDX)      cv4(usdx, gb_usdx, i);
        else if (i < C_BSPN) cv4(bspn, gb_bspn, i - C_USDX);
        else if (i < C_PV)   cv4(pv,   gb_pv,   i - C_BSPN);
        else if (i < C_AW)   cv4(aw,   gb_attnW,i - C_PV);
        else if (i < C_WC)   cv4(wc,   gb_Wc,   i - C_AW);
        else if (i < C_WG) {
            const int j = i - C_WC;
            if (4*j < VV*HH) cv4(wg, gb_Wg, j);
            else *(uint2*)(gb_Wg + 4*(size_t)j) = make_uint2(0u, 0u);
        }
        else if (i < C_WIH)  cv4(wih, gb_Wih, i - C_WG);
        else if (i < C_WHH)  cv4(whh, gb_Whh, i - C_WIH);
        else if (i < C_H0)   cv4(h0,  gb_h0,  i - C_WHH);
        else if (i < C_Q) {
            const int j = (i - C_H0) * 4;
            *(float4*)(g_q + j) = *(const float4*)(attnb + (j & (HH-1)));
        }
        else if (i < C_GEN) {
            const int j = (i - C_Q) * 4;
            *(float4*)(g_gen + j) = *(const float4*)(wgb + (j % VV));
        }
        else if (i < C_ZS)  *(float4*)(g_scores + (i - C_GEN)*4) = make_float4(0,0,0,0);
        else if (i < C_ZC)  *(float4*)(g_cpraw  + (i - C_ZS)*4)  = make_float4(0,0,0,0);
        else if (i < C_ZGI) *(float4*)(g_gi     + (i - C_ZC)*4)  = make_float4(0,0,0,0);
        else                *(float4*)(g_gh     + (i - C_ZGI)*4) = make_float4(0,0,0,0);
    }
}

// =====================================================================
// bf16 HMMA GEMM core: 3-stage cp.async pipeline, ldmatrix fragments.
// C = A @ B^T, per-block tile 128x128, k-tile 32, K%32==0.
// EPI==1: sOut[m] += sum_n dvec[b,n]*tanh(acc + qadd[b,n]), b=m/T
// EPI==2: atomicAdd(C[m,n], acc)   (n<N guarded)
// =====================================================================
#define PADK 40
#define STGB (128*PADK*2)    // 10240 B per stage per matrix
#define SMEMB (6*STGB)       // 61440 B total (3 stages x A,B)

__device__ __forceinline__ void cpa16(unsigned d, const void* s) {
    asm volatile("cp.async.cg.shared.global [%0], [%1], 16;" :: "r"(d), "l"(s));
}
__device__ __forceinline__ void ldsm4(unsigned* r, unsigned a) {
    asm volatile("ldmatrix.sync.aligned.m8n8.x4.shared.b16 {%0,%1,%2,%3}, [%4];"
                 : "=r"(r[0]), "=r"(r[1]), "=r"(r[2]), "=r"(r[3]) : "r"(a));
}

template<int EPI>
__device__ __forceinline__ void gemm_core(
    const bf16* __restrict__ A, int lda,
    const bf16* __restrict__ Bw, int ldb,
    float* __restrict__ C, int ldc,
    int N, int K, int m0, int n0,
    const float* __restrict__ qadd, int qstride,
    const float* __restrict__ dvec, int dstride,
    float* __restrict__ sOut, int T, bf16* smem)
{
    const int tid = threadIdx.x, lane = tid & 31, wid = tid >> 5;
    const int wm = wid >> 2, wn = wid & 3;
    const int g = lane >> 2, tig = lane & 3;
    const unsigned sbase = (unsigned)__cvta_generic_to_shared(smem);

    const int crow = tid >> 2, ci = tid & 3;
    const bf16* aS0 = A  + (size_t)(m0 + crow) * lda + ci*8;
    const bf16* aS1 = aS0 + (size_t)64 * lda;
    const bf16* bS0 = Bw + (size_t)(n0 + crow) * ldb + ci*8;
    const bf16* bS1 = bS0 + (size_t)64 * ldb;
    const unsigned o0 = (crow * PADK + ci*8) * 2;
    const unsigned o1 = o0 + 64*PADK*2;

    const unsigned aF = sbase + ((wm*64 + (lane&15)) * PADK + ((lane>>4)*8)) * 2;
    const unsigned bF = sbase + 3*STGB +
        ((wn*32 + ((lane>>4)*8) + (lane&7)) * PADK + (((lane>>3)&1)*8)) * 2;

    float acc[4][4][4];
#pragma unroll
    for (int i = 0; i < 4; i++)
#pragma unroll
        for (int j = 0; j < 4; j++)
#pragma unroll
            for (int c = 0; c < 4; c++) acc[i][j][c] = 0.f;

    const int KT = K >> 5;

    // prologue: stages 0,1
#pragma unroll
    for (int p = 0; p < 2; p++) {
        const int kk = p << 5;
        const unsigned as = sbase + p*STGB, bs = sbase + 3*STGB + p*STGB;
        cpa16(as + o0, aS0 + kk); cpa16(as + o1, aS1 + kk);
        cpa16(bs + o0, bS0 + kk); cpa16(bs + o1, bS1 + kk);
        asm volatile("cp.async.commit_group;");
    }

    int st = 0, stp = 2;   // compute stage, prefetch stage
    for (int kt = 0; kt < KT; kt++) {
        asm volatile("cp.async.wait_group 1;");
        __syncthreads();

        if (kt + 2 < KT) {
            const int kk = (kt + 2) << 5;
            const unsigned as = sbase + stp*STGB, bs = sbase + 3*STGB + stp*STGB;
            cpa16(as + o0, aS0 + kk); cpa16(as + o1, aS1 + kk);
            cpa16(bs + o0, bS0 + kk); cpa16(bs + o1, bS1 + kk);
        }
        asm volatile("cp.async.commit_group;");

        const unsigned aB = aF + st * STGB;
        const unsigned bB = bF + st * STGB;
#pragma unroll
        for (int ks = 0; ks < 2; ks++) {
            unsigned afr[4][4], bfr[4][2];
#pragma unroll
            for (int mf = 0; mf < 4; mf++)
                ldsm4(afr[mf], aB + mf * (16*PADK*2) + ks * 32);
#pragma unroll
            for (int p = 0; p < 2; p++) {
                unsigned r[4];
                ldsm4(r, bB + p * (16*PADK*2) + ks * 32);
                bfr[2*p][0] = r[0]; bfr[2*p][1] = r[1];
                bfr[2*p+1][0] = r[2]; bfr[2*p+1][1] = r[3];
            }
#pragma unroll
            for (int mf = 0; mf < 4; mf++)
#pragma unroll
                for (int nf = 0; nf < 4; nf++) {
                    asm volatile(
                        "mma.sync.aligned.m16n8k16.row.col.f32.bf16.bf16.f32 "
                        "{%0,%1,%2,%3},{%4,%5,%6,%7},{%8,%9},{%0,%1,%2,%3};"
                        : "+f"(acc[mf][nf][0]), "+f"(acc[mf][nf][1]),
                          "+f"(acc[mf][nf][2]), "+f"(acc[mf][nf][3])
                        : "r"(afr[mf][0]), "r"(afr[mf][1]), "r"(afr[mf][2]), "r"(afr[mf][3]),
                          "r"(bfr[nf][0]), "r"(bfr[nf][1]));
                }
        }
        st = (st == 2) ? 0 : st + 1;
        stp = (stp == 2) ? 0 : stp + 1;
    }

    if (EPI == 2) {
#pragma unroll
        for (int mf = 0; mf < 4; mf++)
#pragma unroll
            for (int rr = 0; rr < 2; rr++) {
                const int m = m0 + wm*64 + mf*16 + g + rr*8;
#pragma unroll
                for (int nf = 0; nf < 4; nf++) {
                    const int n = n0 + wn*32 + nf*8 + 2*tig;
                    if (n < N)     atomicAdd(&C[(size_t)m*ldc + n],     acc[mf][nf][rr*2]);
                    if (n + 1 < N) atomicAdd(&C[(size_t)m*ldc + n + 1], acc[mf][nf][rr*2+1]);
                }
            }
    } else {
#pragma unroll
        for (int mf = 0; mf < 4; mf++)
#pragma unroll
            for (int rr = 0; rr < 2; rr++) {
                const int m = m0 + wm*64 + mf*16 + g + rr*8;
                const int b = m / T;
                const float* q  = qadd + (size_t)b * qstride;
                const float* dv = dvec + (size_t)b * dstride;
                float s = 0.f;
#pragma unroll
                for (int nf = 0; nf < 4; nf++) {
                    const int n = n0 + wn*32 + nf*8 + 2*tig;
                    s += dv[n]   * tanhf(acc[mf][nf][rr*2]   + q[n]);
                    s += dv[n+1] * tanhf(acc[mf][nf][rr*2+1] + q[n+1]);
                }
                s += __shfl_xor_sync(0xffffffffu, s, 1);
                s += __shfl_xor_sync(0xffffffffu, s, 2);
                if (tig == 0) atomicAdd(&sOut[m], s);
            }
    }
}

// generic kernel (split-K via blockIdx.z: each split handles K columns at offset z*K)
template<int EPI>
__global__ __launch_bounds__(256)
void mma_gemm(const bf16* __restrict__ A, int lda,
              const bf16* __restrict__ Bw, int ldb,
              float* __restrict__ C, int ldc,
              int N, int K,
              const float* __restrict__ qadd, int qstride,
              const float* __restrict__ dvec, int dstride,
              float* __restrict__ sOut, int T)
{
    extern __shared__ bf16 smem[];
    const int koff = blockIdx.z * K;
    gemm_core<EPI>(A + koff, lda, Bw + koff, ldb, C, ldc, N, K,
                   blockIdx.y * 128, blockIdx.x * 128,
                   qadd, qstride, dvec, dstride, sOut, T, smem);
}

// batched score GEMM over all three encoders in one launch
__global__ __launch_bounds__(256)
void score_batch(const float* __restrict__ vw)
{
    extern __shared__ bf16 smem[];
    const int by = blockIdx.y;
    const bf16* A; float* sOut; int T, m0;
    if (by < 256)      { A = gb_usdx; sOut = g_scores;               T = TU; m0 = by*128; }
    else if (by < 384) { A = gb_bspn; sOut = g_scores + Bsz*TU;      T = TB; m0 = (by-256)*128; }
    else               { A = gb_pv;   sOut = g_scores + Bsz*(TU+TB); T = TP; m0 = (by-384)*128; }
    gemm_core<1>(A, HH, gb_attnW + HH, 2*HH, nullptr, 0, HH, HH,
                 m0, blockIdx.x * 128, g_q, HH, vw, 0, sOut, T, smem);
}

// ---------------- small kernels ----------------
__global__ void assemble_x(const int* __restrict__ w, const float* __restrict__ emb,
                           const float* __restrict__ db)
{
    const int b = blockIdx.x, tid = threadIdx.x;
    const int wi = w[b];
    gb_x[b*2080 + tid]       = __float2bfloat16(emb[(size_t)wi*HH + tid]);
    gb_x[b*2080 + 256 + tid] = __float2bfloat16(emb[(size_t)wi*HH + 256 + tid]);
    if (tid < 32) gb_x[b*2080 + 2048 + tid] = __float2bfloat16(db[b*32 + tid]);
}

// masked softmax over scores + ctx = a @ enc, written into gb_x
__global__ __launch_bounds__(256)
void ctx_k(const int* __restrict__ idu, const int* __restrict__ idb,
           const int* __restrict__ idp)
{
    const int b = blockIdx.x, e = blockIdx.y, tid = threadIdx.x;
    const bf16* enc; const int* ids; int T, soff;
    if (e == 0)      { enc = gb_usdx; ids = idu; T = TU; soff = 0; }
    else if (e == 1) { enc = gb_bspn; ids = idb; T = TB; soff = Bsz*TU; }
    else             { enc = gb_pv;   ids = idp; T = TP; soff = Bsz*(TU+TB); }

    __shared__ float a[TU];
    __shared__ float red[8];

    float s = -3.4e38f;
    if (tid < T) {
        s = g_scores[soff + b*T + tid];
        if (ids[b*T + tid] == 0) s = NEGV;
    }
    float v = s;
#pragma unroll
    for (int o = 16; o; o >>= 1) v = fmaxf(v, __shfl_xor_sync(~0u, v, o));
    if ((tid & 31) == 0) red[tid >> 5] = v;
    __syncthreads();
    float mx = red[0];
#pragma unroll
    for (int i = 1; i < 8; i++) mx = fmaxf(mx, red[i]);
    __syncthreads();

    const float ex = (tid < T) ? expf(s - mx) : 0.f;
    v = ex;
#pragma unroll
    for (int o = 16; o; o >>= 1) v += __shfl_xor_sync(~0u, v, o);
    if ((tid & 31) == 0) red[tid >> 5] = v;
    __syncthreads();
    float sum = 0.f;
#pragma unroll
    for (int i = 0; i < 8; i++) sum += red[i];
    if (tid < T) a[tid] = ex / sum;
    __syncthreads();

    // ctx: thread handles cols 2*tid, 2*tid+1 via 32-bit loads
    const unsigned* er32 = (const unsigned*)(enc + (size_t)b * T * HH);
    float ax = 0.f, ay = 0.f;
#pragma unroll 4
    for (int t = 0; t < T; t++) {
        const float at = a[t];
        const unsigned u = er32[t*256 + tid];
        const float2 f = __bfloat1622float2(*(const __nv_bfloat162*)&u);
        ax += at * f.x; ay += at * f.y;
    }
    const __nv_bfloat162 r2 = __floats2bfloat162_rn(ax, ay);
    *(unsigned*)(gb_x + b*2080 + 512 + e*HH + 2*tid) = *(const unsigned*)&r2;
}

__global__ void gate_k(const float* __restrict__ h0, const float* __restrict__ bih,
                       const float* __restrict__ bhh)
{
    const int i = blockIdx.x * 256 + threadIdx.x;
    const int b = i >> 9, h = i & (HH - 1);
    const float ir  = g_gi[b*1536 + h]        + bih[h];
    const float hr  = g_gh[b*1536 + h]        + bhh[h];
    const float iz  = g_gi[b*1536 + 512 + h]  + bih[512 + h];
    const float hz  = g_gh[b*1536 + 512 + h]  + bhh[512 + h];
    const float in_ = g_gi[b*1536 + 1024 + h] + bih[1024 + h];
    const float hn  = g_gh[b*1536 + 1024 + h] + bhh[1024 + h];
    const float r = 1.f / (1.f + expf(-(ir + hr)));
    const float z = 1.f / (1.f + expf(-(iz + hz)));
    const float n = tanhf(in_ + r * hn);
    const float hv = (1.f - z) * n + z * h0[i];
    g_hnew[i] = hv;
    gb_hnew[i] = __float2bfloat16(hv);
}

__global__ __launch_bounds__(256)
void final_k(const int* __restrict__ idb, const int* __restrict__ nounk,
             float* __restrict__ out)
{
    const int b = blockIdx.x, tid = threadIdx.x;
    __shared__ float cps[VV + TB];
    __shared__ float add2[VOOVc - VV];
    __shared__ float red[8];

    for (int i = tid; i < VV + TB; i += 256) cps[i] = 0.f;
    for (int i = tid; i < VOOVc - VV; i += 256) add2[i] = 0.f;
    __syncthreads();

    if (tid < TB) {
        float cr = g_cpraw[b*TB + tid];
        if (idb[b*TB + tid] == 0) cr = NEGV;
        const int nk = nounk[b*TB + tid];
        const int col = (nk < VV) ? nk : (VV + tid);
        atomicAdd(&cps[col], cr);
    }
    __syncthreads();

    const float* gb = g_gen + (size_t)b * VV;
    float mx = -3.4e38f;
    for (int i = tid; i < VV; i += 256)       mx = fmaxf(mx, gb[i]);
    for (int i = tid; i < VV + TB; i += 256)  mx = fmaxf(mx, cps[i]);
    float v = mx;
#pragma unroll
    for (int o = 16; o; o >>= 1) v = fmaxf(v, __shfl_xor_sync(~0u, v, o));
    if ((tid & 31) == 0) red[tid >> 5] = v;
    __syncthreads();
    mx = red[0];
#pragma unroll
    for (int i = 1; i < 8; i++) mx = fmaxf(mx, red[i]);
    __syncthreads();

    float se = 0.f;
    for (int i = tid; i < VV; i += 256)       se += expf(gb[i] - mx);
    for (int i = tid; i < VV + TB; i += 256)  se += expf(cps[i] - mx);
    v = se;
#pragma unroll
    for (int o = 16; o; o >>= 1) v += __shfl_xor_sync(~0u, v, o);
    if ((tid & 31) == 0) red[tid >> 5] = v;
    __syncthreads();
    se = 0.f;
#pragma unroll
    for (int i = 0; i < 8; i++) se += red[i];
    const float lz = mx + logf(se);

    float* ob = out + (size_t)b * VOOVc;
    for (int i = tid; i < VV; i += 256) {
        const float ga = gb[i] - lz, cc = cps[i] - lz;
        const float m2 = fmaxf(ga, cc);
        ob[i] = m2 + log1pf(expf(fminf(ga, cc) - m2));
    }
    if (tid < TB) {
        const int nk = nounk[b*TB + tid];
        if (nk >= VV) atomicAdd(&add2[nk - VV], expf(cps[VV + tid] - lz));
    }
    __syncthreads();
    for (int i = tid; i < VOOVc - VV; i += 256) {
        const float a2 = add2[i];
        ob[VV + i] = (a2 > 0.f) ? logf(fmaxf(a2, 1e-38f)) : NEGV;
    }
}

// ---------------- launcher ----------------
extern "C" void kernel_launch(void* const* d_in, const int* in_sizes, int n_in,
                              void* d_out, int out_size)
{
    (void)in_sizes; (void)n_in; (void)out_size;
    const int*   w     = (const int*)  d_in[0];
    const float* h0    = (const float*)d_in[1];
    const float* usdx  = (const float*)d_in[2];
    const float* bspn  = (const float*)d_in[3];
    const float* pv    = (const float*)d_in[4];
    const float* db    = (const float*)d_in[5];
    const int*   idu   = (const int*)  d_in[6];
    const int*   idb   = (const int*)  d_in[7];
    const int*   idp   = (const int*)  d_in[8];
    const int*   nounk = (const int*)  d_in[9];
    const float* emb   = (const float*)d_in[11];
    const float* attnW = (const float*)d_in[12];
    const float* attnb = (const float*)d_in[13];
    const float* vw    = (const float*)d_in[14];
    const float* Wc    = (const float*)d_in[15];
    const float* Wcb   = (const float*)d_in[16];
    const float* Wg    = (const float*)d_in[17];
    const float* Wgb   = (const float*)d_in[18];
    const float* Wih   = (const float*)d_in[19];
    const float* Whh   = (const float*)d_in[20];
    const float* bih   = (const float*)d_in[21];
    const float* bhh   = (const float*)d_in[22];
    float* out = (float*)d_out;

    float *q, *sc, *gi, *gh, *hn, *gen, *cpr;
    bf16 *bU, *bB, *bP, *bAW, *bWc, *bWg, *bWih, *bWhh, *bH0, *bX, *bHn;
    cudaGetSymbolAddress((void**)&q,   g_q);
    cudaGetSymbolAddress((void**)&sc,  g_scores);
    cudaGetSymbolAddress((void**)&gi,  g_gi);
    cudaGetSymbolAddress((void**)&gh,  g_gh);
    cudaGetSymbolAddress((void**)&hn,  g_hnew);
    cudaGetSymbolAddress((void**)&gen, g_gen);
    cudaGetSymbolAddress((void**)&cpr, g_cpraw);
    cudaGetSymbolAddress((void**)&bU,  gb_usdx);
    cudaGetSymbolAddress((void**)&bB,  gb_bspn);
    cudaGetSymbolAddress((void**)&bP,  gb_pv);
    cudaGetSymbolAddress((void**)&bAW, gb_attnW);
    cudaGetSymbolAddress((void**)&bWc, gb_Wc);
    cudaGetSymbolAddress((void**)&bWg, gb_Wg);
    cudaGetSymbolAddress((void**)&bWih,gb_Wih);
    cudaGetSymbolAddress((void**)&bWhh,gb_Whh);
    cudaGetSymbolAddress((void**)&bH0, gb_h0);
    cudaGetSymbolAddress((void**)&bX,  gb_x);
    cudaGetSymbolAddress((void**)&bHn, gb_hnew);

    cudaFuncSetAttribute(mma_gemm<1>, cudaFuncAttributeMaxDynamicSharedMemorySize, SMEMB);
    cudaFuncSetAttribute(mma_gemm<2>, cudaFuncAttributeMaxDynamicSharedMemorySize, SMEMB);
    cudaFuncSetAttribute(score_batch, cudaFuncAttributeMaxDynamicSharedMemorySize, SMEMB);

    // 1. all conversions + inits
    megacvt<<<1184, 256>>>(usdx, bspn, pv, attnW, Wc, Wg, Wih, Whh, h0, attnb, Wgb);

    // 2. assemble x (emb | ... | db)
    assemble_x<<<Bsz, 256>>>(w, emb, db);

    // 3. q += h0 @ W1^T  (split-K x4, q pre-init to attn_b)
    mma_gemm<2><<<dim3(4, 1, 4), 256, SMEMB>>>(bH0, HH, bAW, 2*HH, q, HH,
                                               HH, 128, nullptr, 0, nullptr, 0, nullptr, 1);

    // 4. fused attention logits for all three encoders
    score_batch<<<dim3(4, 448), 256, SMEMB>>>(vw);

    // 5. softmax + ctx into gb_x
    ctx_k<<<dim3(Bsz, 3), 256>>>(idu, idb, idp);

    // 6. GRU input/hidden projections (split-K, atomic, biases folded into gate)
    mma_gemm<2><<<dim3(12, 1, 5), 256, SMEMB>>>(bX, 2080, bWih, 2080, gi, 1536,
                                                1536, 416, nullptr, 0, nullptr, 0, nullptr, 1);
    mma_gemm<2><<<dim3(12, 1, 2), 256, SMEMB>>>(bH0, HH, bWhh, HH, gh, 1536,
                                                1536, 256, nullptr, 0, nullptr, 0, nullptr, 1);
    gate_k<<<Bsz*HH/256, 256>>>(h0, bih, bhh);

    // 7. gen += hnew @ Wg^T  (split-K x2, gen pre-init to Wgen_b)
    mma_gemm<2><<<dim3(24, 1, 2), 256, SMEMB>>>(bHn, HH, bWg, HH, gen, VV,
                                                VV, 256, nullptr, 0, nullptr, 0, nullptr, 1);

    // 8. cp_raw[b,t] = sum_h hnew[b,h]*tanh(bspn@Wc^T + Wcb)
    mma_gemm<1><<<dim3(4, 128), 256, SMEMB>>>(bB, HH, bWc, HH, nullptr, 0,
                                              HH, HH, Wcb, 0, hn, HH, cpr, TB);

    // 9. joint log-softmax + copy-scatter + logaddexp + OOV
    final_k<<<Bsz, 256>>>(idb, nounk, out);
}